// round 1
// baseline (speedup 1.0000x reference)
#include <cuda_runtime.h>

#define NB 64
#define CH 64
#define TT 300
#define VV 25
#define SS 3
#define ICH 16
#define TV 7500            // TT*VV
#define KSPLIT 6

// ---------------- scratch (static device memory; no allocs) ----------------
__device__ float g_T1[SS * NB * ICH * TV];      // 23.04M floats
__device__ float g_T2[SS * NB * ICH * TV];
__device__ float g_Wc[SS * CH * 9 * 32];        // [s][c][kt][ic2] ic2: 0-15 t1, 16-31 t2
__device__ float g_bT1e[SS * ICH];
__device__ float g_bT2e[SS * ICH];
__device__ float g_WdeT[SS * CH * CH];          // [s][c][o], slim-scaled
__device__ float g_btot[CH];
__device__ float g_bnscale[CH];
__device__ float g_bnbias[CH];
__device__ float g_Afull[SS * VV * VV];
__device__ float g_partial[KSPLIT * SS * NB * VV * VV];
__device__ float g_A1[SS * NB * VV * VV];

// ---------------- helpers ----------------
__device__ __forceinline__ float slim16(int ic, const float* w) {
    if (ic < 9)  return 1.f;
    if (ic < 11) return w[1];
    if (ic < 12) return w[2];
    if (ic < 14) return w[3];
    return w[4];
}
__device__ __forceinline__ float slim64(int o, const float* w) {
    if (o < 38) return 1.f;
    if (o < 44) return w[1];
    if (o < 51) return w[2];
    if (o < 57) return w[3];
    return w[4];
}

// ---------------- prep: fold scales, A_full, BN ----------------
__global__ void prep_kernel(const float* __restrict__ w5,
                            const float* __restrict__ A, const float* __restrict__ PA,
                            const float* __restrict__ Wd, const float* __restrict__ bd,
                            const float* __restrict__ WT1, const float* __restrict__ bT1,
                            const float* __restrict__ WT2, const float* __restrict__ bT2,
                            const float* __restrict__ bng, const float* __restrict__ bnb,
                            const float* __restrict__ bnm, const float* __restrict__ bnv)
{
    int tid = threadIdx.x;
    int nt = blockDim.x;

    for (int i = tid; i < SS * VV * VV; i += nt) {
        float a = A[i];
        float a2 = a * a;
        float ach = 8.f * a2 * a2 - 4.f * a2 - 4.f * a;
        int u = (i / VV) % VV, v = i % VV;
        g_Afull[i] = a + PA[i] + ach + (u == v ? 1.f : 0.f);
    }
    for (int i = tid; i < SS * CH * 9 * 32; i += nt) {
        int ic2 = i & 31;
        int kt = (i >> 5) % 9;
        int c  = (i / 288) % CH;
        int s  = i / (288 * CH);
        int ic = ic2 & 15;
        const float* src = (ic2 < 16) ? WT1 : WT2;
        g_Wc[i] = src[((s * ICH + ic) * CH + c) * 9 + kt] * slim16(ic, w5);
    }
    for (int i = tid; i < SS * ICH; i += nt) {
        int ic = i % ICH;
        float sc = slim16(ic, w5);
        g_bT1e[i] = bT1[i] * sc;
        g_bT2e[i] = bT2[i] * sc;
    }
    for (int i = tid; i < SS * CH * CH; i += nt) {
        int o = i % CH;
        int c = (i / CH) % CH;
        int s = i / (CH * CH);
        g_WdeT[i] = Wd[(s * CH + o) * CH + c] * slim64(o, w5);
    }
    for (int i = tid; i < CH; i += nt) {
        float bt = 0.f;
        for (int s = 0; s < SS; ++s) bt += bd[s * CH + i];
        g_btot[i] = bt * slim64(i, w5);
        float inv = rsqrtf(bnv[i] + 1e-5f);
        float bs = bng[i] * inv;
        g_bnscale[i] = bs;
        g_bnbias[i] = bnb[i] - bnm[i] * bs;
    }
}

// ---------------- conv: t1/t2 temporal convs (dominant GEMM) ----------------
// block: (tile 0..29, n, s), 128 threads; each thread: 32 channels x 2 positions
#define CONV_SMEM_FLOATS (16 * 476 + 4608)
__global__ void __launch_bounds__(128) conv_kernel(const float* __restrict__ x)
{
    extern __shared__ float sm[];
    float* xs = sm;              // 16 c x 476 (19 t x 25 v, padded)
    float* ws = sm + 16 * 476;   // 16 c x 9 kt x 32 ic2

    const int tid = threadIdx.x;
    const int t0 = blockIdx.x * 10;
    const int n = blockIdx.y;
    const int s = blockIdx.z;

    float acc[2][32];
#pragma unroll
    for (int a = 0; a < 2; ++a)
#pragma unroll
        for (int b = 0; b < 32; ++b) acc[a][b] = 0.f;

    for (int c0 = 0; c0 < CH; c0 += 16) {
        __syncthreads();
        // x tile: t in [t0-4, t0+15), zero-padded outside [0,300)
        for (int i = tid; i < 16 * 475; i += 128) {
            int cl = i / 475, q = i % 475;
            int t = t0 - 4 + q / 25;
            int v = q % 25;
            float val = 0.f;
            if (t >= 0 && t < TT) val = x[((n * CH + c0 + cl) * TT + t) * VV + v];
            xs[cl * 476 + q] = val;
        }
        // weights: contiguous copy (already repacked in prep)
        const float* wsrc = &g_Wc[(s * CH + c0) * 288];
        for (int i = tid; i < 16 * 288; i += 128) ws[i] = wsrc[i];
        __syncthreads();

#pragma unroll 1
        for (int cl = 0; cl < 16; ++cl) {
#pragma unroll
            for (int kt = 0; kt < 9; ++kt) {
                int xoff = cl * 476 + 2 * tid + kt * 25;
                float x0 = xs[xoff];
                float x1 = xs[xoff + 1];
                const float4* wv = reinterpret_cast<const float4*>(&ws[(cl * 9 + kt) * 32]);
#pragma unroll
                for (int jj = 0; jj < 8; ++jj) {
                    float4 w = wv[jj];
                    acc[0][4 * jj + 0] += w.x * x0;  acc[1][4 * jj + 0] += w.x * x1;
                    acc[0][4 * jj + 1] += w.y * x0;  acc[1][4 * jj + 1] += w.y * x1;
                    acc[0][4 * jj + 2] += w.z * x0;  acc[1][4 * jj + 2] += w.z * x1;
                    acc[0][4 * jj + 3] += w.w * x0;  acc[1][4 * jj + 3] += w.w * x1;
                }
            }
        }
    }

    const int baseT = ((s * NB + n) * ICH) * TV + t0 * 25;
#pragma unroll
    for (int pp = 0; pp < 2; ++pp) {
        int p = 2 * tid + pp;
        if (p < 250) {
#pragma unroll
            for (int ic = 0; ic < 16; ++ic) {
                g_T1[baseT + ic * TV + p] = acc[pp][ic]      + g_bT1e[s * ICH + ic];
                g_T2[baseT + ic * TV + p] = acc[pp][ic + 16] + g_bT2e[s * ICH + ic];
            }
        }
    }
}

// ---------------- attention raw scores: q@k with K-split ----------------
__global__ void __launch_bounds__(128) att_kernel()
{
    __shared__ float t1s[25 * 81];
    __shared__ float t2s[25 * 81];
    const int tid = threadIdx.x;
    const int b = blockIdx.x;    // s*64+n
    const int ky = blockIdx.y;   // 0..KSPLIT-1
    const float* p1 = &g_T1[b * (ICH * TV)];
    const float* p2 = &g_T2[b * (ICH * TV)];

    float acc[5] = {0.f, 0.f, 0.f, 0.f, 0.f};
    const int vk = tid / 5;
    const int j = tid % 5;
    const bool active = tid < 125;

    for (int ch = 0; ch < 10; ++ch) {
        int k0 = ky * 800 + ch * 80;
        __syncthreads();
        for (int i = tid; i < 2000; i += 128) {
            int kl = i / 25, v = i % 25;
            t1s[v * 81 + kl] = p1[k0 * 25 + i];
            t2s[v * 81 + kl] = p2[k0 * 25 + i];
        }
        __syncthreads();
        if (active) {
#pragma unroll 4
            for (int kl = 0; kl < 80; ++kl) {
                float b2 = t2s[vk * 81 + kl];
#pragma unroll
                for (int m = 0; m < 5; ++m)
                    acc[m] += t1s[(j * 5 + m) * 81 + kl] * b2;
            }
        }
    }
    if (active) {
        int outb = (ky * (SS * NB) + b) * 625;
#pragma unroll
        for (int m = 0; m < 5; ++m)
            g_partial[outb + (j * 5 + m) * 25 + vk] = acc[m];
    }
}

// ---------------- softmax over vq + A1 = A_full + att ----------------
__global__ void soft_kernel()
{
    const int b = blockIdx.x;  // s*64+n
    const int vk = threadIdx.x;
    if (vk >= 25) return;
    const int s = b / NB;
    float r[25];
    float mx = -1e30f;
    for (int vq = 0; vq < 25; ++vq) {
        float sum = 0.f;
        for (int ky = 0; ky < KSPLIT; ++ky)
            sum += g_partial[(ky * (SS * NB) + b) * 625 + vq * 25 + vk];
        r[vq] = sum * (1.f / 4800.f);
        mx = fmaxf(mx, r[vq]);
    }
    float e = 0.f;
    for (int vq = 0; vq < 25; ++vq) { r[vq] = expf(r[vq] - mx); e += r[vq]; }
    float inv = 1.f / e;
    for (int vq = 0; vq < 25; ++vq)
        g_A1[b * 625 + vq * 25 + vk] = g_Afull[s * 625 + vq * 25 + vk] + r[vq] * inv;
}

// ---------------- fused: agg = x@A1, z = Wd@agg, sum over s, BN+res+relu ----
// block: (t-tile of 5, n), 256 threads; thread: 4 o x 8 pos register tile
#define Z_SMEM_FLOATS (8192 + 8192 + 4096 + 656)
__global__ void __launch_bounds__(256) z_kernel(const float* __restrict__ x,
                                                float* __restrict__ out)
{
    extern __shared__ float sm[];
    float* xs  = sm;           // 64 c x 128 pos (125 used)
    float* ag  = sm + 8192;    // 64 c x 128 pos
    float* wsm = sm + 16384;   // 64 k x 64 o
    float* a1s = sm + 20480;   // 25 x 26

    const int tid = threadIdx.x;
    const int t0 = blockIdx.x * 5;
    const int n = blockIdx.y;

    for (int i = tid; i < 8192; i += 256) {
        int c = i >> 7, p = i & 127;
        xs[i] = (p < 125) ? x[(n * CH + c) * TV + t0 * 25 + p] : 0.f;
    }

    float acc[4][8];
#pragma unroll
    for (int a = 0; a < 4; ++a)
#pragma unroll
        for (int q = 0; q < 8; ++q) acc[a][q] = 0.f;

    const int i4 = (tid & 15) * 4;  // o base
    const int j8 = (tid >> 4) * 8;  // pos base

    for (int s = 0; s < SS; ++s) {
        __syncthreads();
        for (int i = tid; i < 4096; i += 256) wsm[i] = g_WdeT[s * 4096 + i];
        for (int i = tid; i < 625; i += 256) {
            int vq = i / 25, v = i % 25;
            a1s[vq * 26 + v] = g_A1[(s * NB + n) * 625 + i];
        }
        __syncthreads();
        // stage1: ag[c][p] = sum_u xs[c][t*25+u] * A1[u][v]
        for (int i = tid; i < 8192; i += 256) {
            int c = i >> 7, p = i & 127;
            float sum = 0.f;
            if (p < 125) {
                int tl = p / 25, v = p % 25;
                const float* xr = &xs[(c << 7) + tl * 25];
#pragma unroll
                for (int u = 0; u < 25; ++u)
                    sum += xr[u] * a1s[u * 26 + v];
            }
            ag[i] = sum;
        }
        __syncthreads();
        // stage2: acc[o][p] += sum_k wsm[k][o] * ag[k][p]
#pragma unroll 2
        for (int k = 0; k < 64; ++k) {
            float4 w  = *reinterpret_cast<const float4*>(&wsm[(k << 6) + i4]);
            float4 g0 = *reinterpret_cast<const float4*>(&ag[(k << 7) + j8]);
            float4 g1 = *reinterpret_cast<const float4*>(&ag[(k << 7) + j8 + 4]);
            float wv[4] = {w.x, w.y, w.z, w.w};
            float gv[8] = {g0.x, g0.y, g0.z, g0.w, g1.x, g1.y, g1.z, g1.w};
#pragma unroll
            for (int a = 0; a < 4; ++a)
#pragma unroll
                for (int q = 0; q < 8; ++q)
                    acc[a][q] += wv[a] * gv[q];
        }
    }

#pragma unroll
    for (int a = 0; a < 4; ++a) {
        int o = i4 + a;
        float bs = g_bnscale[o], bb = g_bnbias[o], bt = g_btot[o];
#pragma unroll
        for (int q = 0; q < 8; ++q) {
            int p = j8 + q;
            if (p < 125) {
                float val = fmaf(acc[a][q] + bt, bs, bb) + xs[(o << 7) + p];
                out[(n * CH + o) * TV + t0 * 25 + p] = fmaxf(val, 0.f);
            }
        }
    }
}

// ---------------- launch ----------------
extern "C" void kernel_launch(void* const* d_in, const int* in_sizes, int n_in,
                              void* d_out, int out_size)
{
    const float* x   = (const float*)d_in[0];
    const float* w5  = (const float*)d_in[1];
    const float* A   = (const float*)d_in[2];
    const float* PA  = (const float*)d_in[3];
    const float* Wd  = (const float*)d_in[4];
    const float* bd  = (const float*)d_in[5];
    const float* WT1 = (const float*)d_in[6];
    const float* bT1 = (const float*)d_in[7];
    const float* WT2 = (const float*)d_in[8];
    const float* bT2 = (const float*)d_in[9];
    const float* bng = (const float*)d_in[10];
    const float* bnb = (const float*)d_in[11];
    const float* bnm = (const float*)d_in[12];
    const float* bnv = (const float*)d_in[13];
    float* out = (float*)d_out;

    const int conv_smem = CONV_SMEM_FLOATS * 4;
    const int z_smem    = Z_SMEM_FLOATS * 4;
    cudaFuncSetAttribute(conv_kernel, cudaFuncAttributeMaxDynamicSharedMemorySize, conv_smem);
    cudaFuncSetAttribute(z_kernel,    cudaFuncAttributeMaxDynamicSharedMemorySize, z_smem);

    prep_kernel<<<1, 256>>>(w5, A, PA, Wd, bd, WT1, bT1, WT2, bT2, bng, bnb, bnm, bnv);
    conv_kernel<<<dim3(30, NB, SS), 128, conv_smem>>>(x);
    att_kernel<<<dim3(SS * NB, KSPLIT), 128>>>();
    soft_kernel<<<SS * NB, 32>>>();
    z_kernel<<<dim3(60, NB), 256, z_smem>>>(x, out);
}

// round 4
// speedup vs baseline: 1.3607x; 1.3607x over previous
#include <cuda_runtime.h>
#include <stdint.h>

#define NB 64
#define CH 64
#define TT 300
#define VV 25
#define SS 3
#define ICH 16
#define TV 7500
#define KSPLIT 6

// ---------------- scratch ----------------
__device__ float g_T1[SS * NB * ICH * TV];
__device__ float g_T2[SS * NB * ICH * TV];
__device__ __align__(16) uint32_t g_Wb[9 * 64 * 96];   // [kt][c64][n96], tf32 bits
__device__ float g_bT1e[SS * ICH];
__device__ float g_bT2e[SS * ICH];
__device__ float g_WdeT[SS * CH * CH];
__device__ float g_btot[CH];
__device__ float g_bnscale[CH];
__device__ float g_bnbias[CH];
__device__ float g_Afull[SS * VV * VV];
__device__ float g_partial[KSPLIT * SS * NB * VV * VV];
__device__ float g_A1[SS * NB * VV * VV];

// ---------------- helpers ----------------
__device__ __forceinline__ uint32_t f2tf32(float f) {
    uint32_t r;
    asm("cvt.rna.tf32.f32 %0, %1;" : "=r"(r) : "f"(f));
    return r;
}
__device__ __forceinline__ uint32_t smem_u32(const void* p) {
    uint32_t a;
    asm("{ .reg .u64 t; cvta.to.shared.u64 t, %1; cvt.u32.u64 %0, t; }" : "=r"(a) : "l"(p));
    return a;
}
__device__ __forceinline__ void cp16(uint32_t dst, const void* src) {
    asm volatile("cp.async.cg.shared.global [%0], [%1], 16;" :: "r"(dst), "l"(src));
}
__device__ __forceinline__ void cp_commit() {
    asm volatile("cp.async.commit_group;" ::: "memory");
}
template <int N>
__device__ __forceinline__ void cp_wait() {
    asm volatile("cp.async.wait_group %0;" :: "n"(N) : "memory");
}
__device__ __forceinline__ void mma_tf32(float* c, const uint32_t* a, const uint32_t* b) {
    asm volatile(
        "mma.sync.aligned.m16n8k8.row.col.f32.tf32.tf32.f32 "
        "{%0,%1,%2,%3}, {%4,%5,%6,%7}, {%8,%9}, {%0,%1,%2,%3};"
        : "+f"(c[0]), "+f"(c[1]), "+f"(c[2]), "+f"(c[3])
        : "r"(a[0]), "r"(a[1]), "r"(a[2]), "r"(a[3]), "r"(b[0]), "r"(b[1]));
}
__device__ __forceinline__ float slim16(int ic, const float* w) {
    if (ic < 9)  return 1.f;
    if (ic < 11) return w[1];
    if (ic < 12) return w[2];
    if (ic < 14) return w[3];
    return w[4];
}
__device__ __forceinline__ float slim64(int o, const float* w) {
    if (o < 38) return 1.f;
    if (o < 44) return w[1];
    if (o < 51) return w[2];
    if (o < 57) return w[3];
    return w[4];
}

// ---------------- prep ----------------
__global__ void prep_kernel(const float* __restrict__ w5,
                            const float* __restrict__ A, const float* __restrict__ PA,
                            const float* __restrict__ Wd, const float* __restrict__ bd,
                            const float* __restrict__ WT1, const float* __restrict__ bT1,
                            const float* __restrict__ WT2, const float* __restrict__ bT2,
                            const float* __restrict__ bng, const float* __restrict__ bnb,
                            const float* __restrict__ bnm, const float* __restrict__ bnv)
{
    int tid = threadIdx.x;
    int nt = blockDim.x;

    for (int i = tid; i < SS * VV * VV; i += nt) {
        float a = A[i];
        float a2 = a * a;
        float ach = 8.f * a2 * a2 - 4.f * a2 - 4.f * a;
        int u = (i / VV) % VV, v = i % VV;
        g_Afull[i] = a + PA[i] + ach + (u == v ? 1.f : 0.f);
    }
    // B pack: [kt][c][n96], n96 = s*32 + ic2 (ic2 0-15 -> t1, 16-31 -> t2)
    for (int i = tid; i < 9 * 64 * 96; i += nt) {
        int n96 = i % 96;
        int c = (i / 96) % 64;
        int kt = i / (96 * 64);
        int s = n96 >> 5;
        int ic2 = n96 & 31;
        int ic = ic2 & 15;
        const float* src = (ic2 < 16) ? WT1 : WT2;
        float val = src[((s * ICH + ic) * CH + c) * 9 + kt] * slim16(ic, w5);
        g_Wb[i] = f2tf32(val);
    }
    for (int i = tid; i < SS * ICH; i += nt) {
        int ic = i % ICH;
        float sc = slim16(ic, w5);
        g_bT1e[i] = bT1[i] * sc;
        g_bT2e[i] = bT2[i] * sc;
    }
    for (int i = tid; i < SS * CH * CH; i += nt) {
        int o = i % CH;
        int c = (i / CH) % CH;
        int s = i / (CH * CH);
        g_WdeT[i] = Wd[(s * CH + o) * CH + c] * slim64(o, w5);
    }
    for (int i = tid; i < CH; i += nt) {
        float bt = 0.f;
        for (int s = 0; s < SS; ++s) bt += bd[s * CH + i];
        g_btot[i] = bt * slim64(i, w5);
        float inv = rsqrtf(bnv[i] + 1e-5f);
        float bs = bng[i] * inv;
        g_bnscale[i] = bs;
        g_bnbias[i] = bnb[i] - bnm[i] * bs;
    }
}

// ---------------- mma.sync tf32 conv ----------------
// CTA = (t-tile of 8, n). D[256 x 96] (rows: 8t*25v padded to 256), K = 64c x 9kt.
// xs: [c64][row456] tf32, rows = (t0-4+r/25, r%25) for r<400, zeros beyond.
#define ROWPAD 456
#define XS_FLOATS (64 * ROWPAD)
#define BS_STRIDE 104
#define BS_FLOATS (64 * BS_STRIDE)
#define CONV_SMEM ((XS_FLOATS + 2 * BS_FLOATS) * 4)

__global__ void __launch_bounds__(256, 1) tc_conv(const float* __restrict__ x)
{
    extern __shared__ uint32_t sm[];
    uint32_t* xs = sm;                       // XS_FLOATS
    uint32_t* bs = sm + XS_FLOATS;           // 2 stages of BS_FLOATS
    const uint32_t sb = smem_u32(sm);
    const uint32_t bs_addr = sb + XS_FLOATS * 4;

    const int tid = threadIdx.x;
    const int warp = tid >> 5;
    const int lane = tid & 31;
    const int lr = lane & 3;     // k within 4
    const int lq = lane >> 2;    // row/col group
    const int wm = warp & 3;     // M warp (64 rows)
    const int wn = warp >> 2;    // N warp (48 cols)
    const int t0 = blockIdx.x * 8;
    const int n = blockIdx.y;

    // ---- load xs (x tile, tf32) ----
    for (int c = warp; c < 64; c += 8) {
        const float* xr = x + ((n * CH + c) * TT + (t0 - 4)) * VV;
        for (int r = lane; r < ROWPAD; r += 32) {
            float v = 0.f;
            if (r < 400) {
                int t = t0 - 4 + r / 25;
                if (t >= 0 && t < TT) v = xr[r];
            }
            xs[c * ROWPAD + r] = f2tf32(v);
        }
    }

    // ---- issue B[kt=0] ----
    {
        for (int j = 0; j < 6; ++j) {
            int f = tid + j * 256;                 // float4 index, 0..1535
            int c = f / 24, off = (f % 24) * 4;
            cp16(bs_addr + (c * BS_STRIDE + off) * 4, g_Wb + f * 4);
        }
        cp_commit();
    }

    float acc[4][6][4];
#pragma unroll
    for (int mi = 0; mi < 4; ++mi)
#pragma unroll
        for (int ni = 0; ni < 6; ++ni)
#pragma unroll
            for (int q = 0; q < 4; ++q) acc[mi][ni][q] = 0.f;

#pragma unroll 1
    for (int kt = 0; kt < 9; ++kt) {
        __syncthreads();  // prev compute done -> safe to overwrite other buffer
        if (kt < 8) {
            const uint32_t dstb = bs_addr + ((kt + 1) & 1) * BS_FLOATS * 4;
            const uint32_t* src = g_Wb + (kt + 1) * 6144;
            for (int j = 0; j < 6; ++j) {
                int f = tid + j * 256;
                int c = f / 24, off = (f % 24) * 4;
                cp16(dstb + (c * BS_STRIDE + off) * 4, src + f * 4);
            }
            cp_commit();
            cp_wait<1>();
        } else {
            cp_wait<0>();
        }
        __syncthreads();  // B[kt] visible

        const uint32_t* bsl = bs + (kt & 1) * BS_FLOATS;
        const int rowoff = kt * 25 + lq;

#pragma unroll
        for (int k8 = 0; k8 < 8; ++k8) {
            const int kb = k8 * 8;
            uint32_t af[4][4];
#pragma unroll
            for (int mi = 0; mi < 4; ++mi) {
                int R = wm * 64 + mi * 16 + rowoff;
                const uint32_t* p0 = &xs[(kb + lr) * ROWPAD + R];
                af[mi][0] = p0[0];
                af[mi][1] = p0[8];
                af[mi][2] = p0[4 * ROWPAD];
                af[mi][3] = p0[4 * ROWPAD + 8];
            }
            uint32_t bf[6][2];
#pragma unroll
            for (int ni = 0; ni < 6; ++ni) {
                int cb = wn * 48 + ni * 8 + lq;
                bf[ni][0] = bsl[(kb + lr) * BS_STRIDE + cb];
                bf[ni][1] = bsl[(kb + lr + 4) * BS_STRIDE + cb];
            }
#pragma unroll
            for (int mi = 0; mi < 4; ++mi)
#pragma unroll
                for (int ni = 0; ni < 6; ++ni)
                    mma_tf32(acc[mi][ni], af[mi], bf[ni]);
        }
    }

    // ---- epilogue: scatter to g_T1 / g_T2 with bias ----
#pragma unroll
    for (int mi = 0; mi < 4; ++mi) {
        const int rb = wm * 64 + mi * 16 + lq;
#pragma unroll
        for (int ni = 0; ni < 6; ++ni) {
            const int cb = wn * 48 + ni * 8 + 2 * lr;
#pragma unroll
            for (int q = 0; q < 4; ++q) {
                int row = rb + (q >> 1) * 8;
                int col = cb + (q & 1);
                if (row < 200 && t0 * 25 + row < TV) {
                    int s = col >> 5;
                    int ic2 = col & 31;
                    int ic = ic2 & 15;
                    float bias, *dst;
                    if (ic2 < 16) { bias = g_bT1e[s * ICH + ic]; dst = g_T1; }
                    else          { bias = g_bT2e[s * ICH + ic]; dst = g_T2; }
                    dst[((s * NB + n) * ICH + ic) * TV + t0 * 25 + row] = acc[mi][ni][q] + bias;
                }
            }
        }
    }
}

// ---------------- attention raw scores ----------------
__global__ void __launch_bounds__(128) att_kernel()
{
    __shared__ float t1s[25 * 81];
    __shared__ float t2s[25 * 81];
    const int tid = threadIdx.x;
    const int b = blockIdx.x;
    const int ky = blockIdx.y;
    const float* p1 = &g_T1[b * (ICH * TV)];
    const float* p2 = &g_T2[b * (ICH * TV)];

    float acc[5] = {0.f, 0.f, 0.f, 0.f, 0.f};
    const int vk = tid / 5;
    const int j = tid % 5;
    const bool active = tid < 125;

    for (int chk = 0; chk < 10; ++chk) {
        int k0 = ky * 800 + chk * 80;
        __syncthreads();
        for (int i = tid; i < 2000; i += 128) {
            int kl = i / 25, v = i % 25;
            t1s[v * 81 + kl] = p1[k0 * 25 + i];
            t2s[v * 81 + kl] = p2[k0 * 25 + i];
        }
        __syncthreads();
        if (active) {
#pragma unroll 4
            for (int kl = 0; kl < 80; ++kl) {
                float b2 = t2s[vk * 81 + kl];
#pragma unroll
                for (int m = 0; m < 5; ++m)
                    acc[m] += t1s[(j * 5 + m) * 81 + kl] * b2;
            }
        }
    }
    if (active) {
        int outb = (ky * (SS * NB) + b) * 625;
#pragma unroll
        for (int m = 0; m < 5; ++m)
            g_partial[outb + (j * 5 + m) * 25 + vk] = acc[m];
    }
}

// ---------------- softmax + A1 ----------------
__global__ void soft_kernel()
{
    const int b = blockIdx.x;
    const int vk = threadIdx.x;
    if (vk >= 25) return;
    const int s = b / NB;
    float r[25];
    float mx = -1e30f;
    for (int vq = 0; vq < 25; ++vq) {
        float sum = 0.f;
        for (int ky = 0; ky < KSPLIT; ++ky)
            sum += g_partial[(ky * (SS * NB) + b) * 625 + vq * 25 + vk];
        r[vq] = sum * (1.f / 4800.f);
        mx = fmaxf(mx, r[vq]);
    }
    float e = 0.f;
    for (int vq = 0; vq < 25; ++vq) { r[vq] = expf(r[vq] - mx); e += r[vq]; }
    float inv = 1.f / e;
    for (int vq = 0; vq < 25; ++vq)
        g_A1[b * 625 + vq * 25 + vk] = g_Afull[s * 625 + vq * 25 + vk] + r[vq] * inv;
}

// ---------------- fused final ----------------
#define Z_SMEM_FLOATS (8192 + 8192 + 4096 + 656)
__global__ void __launch_bounds__(256) z_kernel(const float* __restrict__ x,
                                                float* __restrict__ out)
{
    extern __shared__ float smz[];
    float* xs  = smz;
    float* ag  = smz + 8192;
    float* wsm = smz + 16384;
    float* a1s = smz + 20480;

    const int tid = threadIdx.x;
    const int t0 = blockIdx.x * 5;
    const int n = blockIdx.y;

    for (int i = tid; i < 8192; i += 256) {
        int c = i >> 7, p = i & 127;
        xs[i] = (p < 125) ? x[(n * CH + c) * TV + t0 * 25 + p] : 0.f;
    }

    float acc[4][8];
#pragma unroll
    for (int a = 0; a < 4; ++a)
#pragma unroll
        for (int q = 0; q < 8; ++q) acc[a][q] = 0.f;

    const int i4 = (tid & 15) * 4;
    const int j8 = (tid >> 4) * 8;

    for (int s = 0; s < SS; ++s) {
        __syncthreads();
        for (int i = tid; i < 4096; i += 256) wsm[i] = g_WdeT[s * 4096 + i];
        for (int i = tid; i < 625; i += 256) {
            int vq = i / 25, v = i % 25;
            a1s[vq * 26 + v] = g_A1[(s * NB + n) * 625 + i];
        }
        __syncthreads();
        for (int i = tid; i < 8192; i += 256) {
            int c = i >> 7, p = i & 127;
            float sum = 0.f;
            if (p < 125) {
                int tl = p / 25, v = p % 25;
                const float* xr = &xs[(c << 7) + tl * 25];
#pragma unroll
                for (int u = 0; u < 25; ++u)
                    sum += xr[u] * a1s[u * 26 + v];
            }
            ag[i] = sum;
        }
        __syncthreads();
#pragma unroll 2
        for (int k = 0; k < 64; ++k) {
            float4 w  = *reinterpret_cast<const float4*>(&wsm[(k << 6) + i4]);
            float4 g0 = *reinterpret_cast<const float4*>(&ag[(k << 7) + j8]);
            float4 g1 = *reinterpret_cast<const float4*>(&ag[(k << 7) + j8 + 4]);
            float wv[4] = {w.x, w.y, w.z, w.w};
            float gv[8] = {g0.x, g0.y, g0.z, g0.w, g1.x, g1.y, g1.z, g1.w};
#pragma unroll
            for (int a = 0; a < 4; ++a)
#pragma unroll
                for (int q = 0; q < 8; ++q)
                    acc[a][q] += wv[a] * gv[q];
        }
    }

#pragma unroll
    for (int a = 0; a < 4; ++a) {
        int o = i4 + a;
        float bsn = g_bnscale[o], bb = g_bnbias[o], bt = g_btot[o];
#pragma unroll
        for (int q = 0; q < 8; ++q) {
            int p = j8 + q;
            if (p < 125) {
                float val = fmaf(acc[a][q] + bt, bsn, bb) + xs[(o << 7) + p];
                out[(n * CH + o) * TV + t0 * 25 + p] = fmaxf(val, 0.f);
            }
        }
    }
}

// ---------------- launch ----------------
extern "C" void kernel_launch(void* const* d_in, const int* in_sizes, int n_in,
                              void* d_out, int out_size)
{
    const float* x   = (const float*)d_in[0];
    const float* w5  = (const float*)d_in[1];
    const float* A   = (const float*)d_in[2];
    const float* PA  = (const float*)d_in[3];
    const float* Wd  = (const float*)d_in[4];
    const float* bd  = (const float*)d_in[5];
    const float* WT1 = (const float*)d_in[6];
    const float* bT1 = (const float*)d_in[7];
    const float* WT2 = (const float*)d_in[8];
    const float* bT2 = (const float*)d_in[9];
    const float* bng = (const float*)d_in[10];
    const float* bnb = (const float*)d_in[11];
    const float* bnm = (const float*)d_in[12];
    const float* bnv = (const float*)d_in[13];
    float* out = (float*)d_out;

    const int z_smem = Z_SMEM_FLOATS * 4;
    cudaFuncSetAttribute(tc_conv, cudaFuncAttributeMaxDynamicSharedMemorySize, CONV_SMEM);
    cudaFuncSetAttribute(z_kernel, cudaFuncAttributeMaxDynamicSharedMemorySize, z_smem);

    prep_kernel<<<1, 256>>>(w5, A, PA, Wd, bd, WT1, bT1, WT2, bT2, bng, bnb, bnm, bnv);
    tc_conv<<<dim3(38, NB), 256, CONV_SMEM>>>(x);
    att_kernel<<<dim3(SS * NB, KSPLIT), 128>>>();
    soft_kernel<<<SS * NB, 32>>>();
    z_kernel<<<dim3(60, NB), 256, z_smem>>>(x, out);
}

// round 6
// speedup vs baseline: 2.2909x; 1.6836x over previous
#include <cuda_runtime.h>
#include <stdint.h>

#define NB 64
#define CH 64
#define TT 300
#define VV 25
#define SS 3
#define ICH 16
#define TV 7500
#define KSPLIT 6

// ---------------- scratch ----------------
__device__ float g_T1[SS * NB * ICH * TV];
__device__ float g_T2[SS * NB * ICH * TV];
__device__ __align__(16) uint32_t g_Wb2[9 * 32 * 96];  // [kt][c2][n96] bf16x2 (lo=c even, hi=c odd)
__device__ float g_bT1e[SS * ICH];
__device__ float g_bT2e[SS * ICH];
__device__ float g_WdeT[SS * CH * CH];                 // [s][c][o]
__device__ float g_btot[CH];
__device__ float g_bnscale[CH];
__device__ float g_bnbias[CH];
__device__ float g_Afull[SS * VV * VV];
__device__ float g_partial[KSPLIT * SS * NB * VV * VV];
__device__ float g_A1[SS * NB * VV * VV];

// ---------------- helpers ----------------
__device__ __forceinline__ uint32_t f2tf32(float f) {
    uint32_t r;
    asm("cvt.rna.tf32.f32 %0, %1;" : "=r"(r) : "f"(f));
    return r;
}
__device__ __forceinline__ uint32_t pack_bf16x2(float lo, float hi) {
    uint32_t r;
    asm("cvt.rn.bf16x2.f32 %0, %1, %2;" : "=r"(r) : "f"(hi), "f"(lo));
    return r;
}
__device__ __forceinline__ uint32_t smem_u32(const void* p) {
    uint32_t a;
    asm("{ .reg .u64 t; cvta.to.shared.u64 t, %1; cvt.u32.u64 %0, t; }" : "=r"(a) : "l"(p));
    return a;
}
__device__ __forceinline__ void cp16(uint32_t dst, const void* src) {
    asm volatile("cp.async.cg.shared.global [%0], [%1], 16;" :: "r"(dst), "l"(src));
}
__device__ __forceinline__ void cp_commit() {
    asm volatile("cp.async.commit_group;" ::: "memory");
}
template <int N>
__device__ __forceinline__ void cp_wait() {
    asm volatile("cp.async.wait_group %0;" :: "n"(N) : "memory");
}
// m16n8k16 bf16: {a0..a3} x {b0,b1} -> 4 f32
__device__ __forceinline__ void mma_bf16(float* c, const uint32_t* a, const uint32_t* b) {
    asm volatile(
        "mma.sync.aligned.m16n8k16.row.col.f32.bf16.bf16.f32 "
        "{%0,%1,%2,%3}, {%4,%5,%6,%7}, {%8,%9}, {%0,%1,%2,%3};"
        : "+f"(c[0]), "+f"(c[1]), "+f"(c[2]), "+f"(c[3])
        : "r"(a[0]), "r"(a[1]), "r"(a[2]), "r"(a[3]), "r"(b[0]), "r"(b[1]));
}
// m16n8k8 tf32
__device__ __forceinline__ void mma_tf32(float* c, const uint32_t* a, const uint32_t* b) {
    asm volatile(
        "mma.sync.aligned.m16n8k8.row.col.f32.tf32.tf32.f32 "
        "{%0,%1,%2,%3}, {%4,%5,%6,%7}, {%8,%9}, {%0,%1,%2,%3};"
        : "+f"(c[0]), "+f"(c[1]), "+f"(c[2]), "+f"(c[3])
        : "r"(a[0]), "r"(a[1]), "r"(a[2]), "r"(a[3]), "r"(b[0]), "r"(b[1]));
}
__device__ __forceinline__ float slim16(int ic, const float* w) {
    if (ic < 9)  return 1.f;
    if (ic < 11) return w[1];
    if (ic < 12) return w[2];
    if (ic < 14) return w[3];
    return w[4];
}
__device__ __forceinline__ float slim64(int o, const float* w) {
    if (o < 38) return 1.f;
    if (o < 44) return w[1];
    if (o < 51) return w[2];
    if (o < 57) return w[3];
    return w[4];
}

// ---------------- prep ----------------
__global__ void prep_kernel(const float* __restrict__ w5,
                            const float* __restrict__ A, const float* __restrict__ PA,
                            const float* __restrict__ Wd, const float* __restrict__ bd,
                            const float* __restrict__ WT1, const float* __restrict__ bT1,
                            const float* __restrict__ WT2, const float* __restrict__ bT2,
                            const float* __restrict__ bng, const float* __restrict__ bnb,
                            const float* __restrict__ bnm, const float* __restrict__ bnv)
{
    int tid = threadIdx.x + blockIdx.x * blockDim.x;
    int nt = blockDim.x * gridDim.x;

    for (int i = tid; i < SS * VV * VV; i += nt) {
        float a = A[i];
        float a2 = a * a;
        float ach = 8.f * a2 * a2 - 4.f * a2 - 4.f * a;
        int u = (i / VV) % VV, v = i % VV;
        g_Afull[i] = a + PA[i] + ach + (u == v ? 1.f : 0.f);
    }
    // B pack: [kt][c2][n96], n96 = s*32 + ic2 (ic2 0-15 -> t1, 16-31 -> t2)
    for (int i = tid; i < 9 * 32 * 96; i += nt) {
        int n96 = i % 96;
        int c2 = (i / 96) % 32;
        int kt = i / (96 * 32);
        int s = n96 >> 5;
        int ic2 = n96 & 31;
        int ic = ic2 & 15;
        const float* src = (ic2 < 16) ? WT1 : WT2;
        float sc = slim16(ic, w5);
        float v0 = src[((s * ICH + ic) * CH + 2 * c2) * 9 + kt] * sc;
        float v1 = src[((s * ICH + ic) * CH + 2 * c2 + 1) * 9 + kt] * sc;
        g_Wb2[i] = pack_bf16x2(v0, v1);
    }
    for (int i = tid; i < SS * ICH; i += nt) {
        int ic = i % ICH;
        float sc = slim16(ic, w5);
        g_bT1e[i] = bT1[i] * sc;
        g_bT2e[i] = bT2[i] * sc;
    }
    for (int i = tid; i < SS * CH * CH; i += nt) {
        int o = i % CH;
        int c = (i / CH) % CH;
        int s = i / (CH * CH);
        g_WdeT[i] = Wd[(s * CH + o) * CH + c] * slim64(o, w5);
    }
    for (int i = tid; i < CH; i += nt) {
        float bt = 0.f;
        for (int s = 0; s < SS; ++s) bt += bd[s * CH + i];
        g_btot[i] = bt * slim64(i, w5);
        float inv = rsqrtf(bnv[i] + 1e-5f);
        float bs = bng[i] * inv;
        g_bnscale[i] = bs;
        g_bnbias[i] = bnb[i] - bnm[i] * bs;
    }
}

// ---------------- bf16 mma conv ----------------
// CTA = (4-t tile, n). D[128 x 96] rows = 4t*25v (100 used), K = 64c x 9kt.
// xs2: bf16x2 [c2=32][XROWS], rows r -> (t0-4 + r/25, r%25), r<300 valid.
#define XROWS 328
#define XS2_U32 (32 * XROWS)
#define BSTR 104
#define BS2_U32 (32 * BSTR)
#define CONV_SMEM ((XS2_U32 + 2 * BS2_U32) * 4)

__global__ void __launch_bounds__(256, 2) tc_conv(const float* __restrict__ x)
{
    extern __shared__ uint32_t sm[];
    uint32_t* xs = sm;
    uint32_t* bs = sm + XS2_U32;
    const uint32_t bs_addr = smem_u32(sm) + XS2_U32 * 4;

    const int tid = threadIdx.x;
    const int warp = tid >> 5;
    const int lane = tid & 31;
    const int lr = lane & 3;
    const int lq = lane >> 2;
    const int wm = warp & 3;     // 32 rows each
    const int wn = warp >> 2;    // 48 cols each
    const int t0 = blockIdx.x * 4;
    const int n = blockIdx.y;

    // ---- load xs (bf16x2 packed channel pairs) ----
    for (int c2 = warp; c2 < 32; c2 += 8) {
        const float* x0 = x + ((n * CH + 2 * c2) * TT + (t0 - 4)) * VV;
        for (int r = lane; r < XROWS; r += 32) {
            float v0 = 0.f, v1 = 0.f;
            if (r < 300) {
                int t = t0 - 4 + r / 25;
                if (t >= 0 && t < TT) { v0 = x0[r]; v1 = x0[r + TT * VV]; }
            }
            xs[c2 * XROWS + r] = pack_bf16x2(v0, v1);
        }
    }

    // ---- issue B[kt=0] ----
#pragma unroll
    for (int j = 0; j < 3; ++j) {
        int f = tid + j * 256;            // 768 float4
        int c2 = f / 24, off = (f % 24) * 4;
        cp16(bs_addr + (c2 * BSTR + off) * 4, g_Wb2 + c2 * 96 + off);
    }
    cp_commit();

    float acc[2][6][4];
#pragma unroll
    for (int mi = 0; mi < 2; ++mi)
#pragma unroll
        for (int ni = 0; ni < 6; ++ni)
#pragma unroll
            for (int q = 0; q < 4; ++q) acc[mi][ni][q] = 0.f;

#pragma unroll 1
    for (int kt = 0; kt < 9; ++kt) {
        __syncthreads();
        if (kt < 8) {
            const uint32_t dstb = bs_addr + ((kt + 1) & 1) * BS2_U32 * 4;
            const uint32_t* src = g_Wb2 + (kt + 1) * 3072;
#pragma unroll
            for (int j = 0; j < 3; ++j) {
                int f = tid + j * 256;
                int c2 = f / 24, off = (f % 24) * 4;
                cp16(dstb + (c2 * BSTR + off) * 4, src + c2 * 96 + off);
            }
            cp_commit();
            cp_wait<1>();
        } else {
            cp_wait<0>();
        }
        __syncthreads();

        const uint32_t* bsl = bs + (kt & 1) * BS2_U32;
        const int rowoff = kt * 25 + lq;

#pragma unroll
        for (int ks = 0; ks < 4; ++ks) {
            const int kb2 = ks * 8;
            uint32_t af[2][4];
#pragma unroll
            for (int mi = 0; mi < 2; ++mi) {
                int R = wm * 32 + mi * 16 + rowoff;
                const uint32_t* p0 = &xs[(kb2 + lr) * XROWS + R];
                af[mi][0] = p0[0];
                af[mi][1] = p0[8];
                af[mi][2] = p0[4 * XROWS];
                af[mi][3] = p0[4 * XROWS + 8];
            }
            uint32_t bf[6][2];
#pragma unroll
            for (int ni = 0; ni < 6; ++ni) {
                int cb = wn * 48 + ni * 8 + lq;
                bf[ni][0] = bsl[(kb2 + lr) * BSTR + cb];
                bf[ni][1] = bsl[(kb2 + lr + 4) * BSTR + cb];
            }
#pragma unroll
            for (int mi = 0; mi < 2; ++mi)
#pragma unroll
                for (int ni = 0; ni < 6; ++ni)
                    mma_bf16(acc[mi][ni], af[mi], bf[ni]);
        }
    }

    // ---- epilogue ----
#pragma unroll
    for (int mi = 0; mi < 2; ++mi) {
        const int rb = wm * 32 + mi * 16 + lq;
#pragma unroll
        for (int ni = 0; ni < 6; ++ni) {
            const int cb = wn * 48 + ni * 8 + 2 * lr;
#pragma unroll
            for (int q = 0; q < 4; ++q) {
                int row = rb + (q >> 1) * 8;
                int col = cb + (q & 1);
                if (row < 100) {
                    int s = col >> 5;
                    int ic2 = col & 31;
                    int ic = ic2 & 15;
                    float bias, *dst;
                    if (ic2 < 16) { bias = g_bT1e[s * ICH + ic]; dst = g_T1; }
                    else          { bias = g_bT2e[s * ICH + ic]; dst = g_T2; }
                    dst[((s * NB + n) * ICH + ic) * TV + t0 * 25 + row] = acc[mi][ni][q] + bias;
                }
            }
        }
    }
}

// ---------------- attention raw scores ----------------
__global__ void __launch_bounds__(128) att_kernel()
{
    __shared__ float t1s[25 * 81];
    __shared__ float t2s[25 * 81];
    const int tid = threadIdx.x;
    const int b = blockIdx.x;
    const int ky = blockIdx.y;
    const float* p1 = &g_T1[b * (ICH * TV)];
    const float* p2 = &g_T2[b * (ICH * TV)];

    float acc[5] = {0.f, 0.f, 0.f, 0.f, 0.f};
    const int vk = tid / 5;
    const int j = tid % 5;
    const bool active = tid < 125;

    for (int chk = 0; chk < 10; ++chk) {
        int k0 = ky * 800 + chk * 80;
        __syncthreads();
        for (int i = tid; i < 2000; i += 128) {
            int kl = i / 25, v = i % 25;
            t1s[v * 81 + kl] = p1[k0 * 25 + i];
            t2s[v * 81 + kl] = p2[k0 * 25 + i];
        }
        __syncthreads();
        if (active) {
#pragma unroll 4
            for (int kl = 0; kl < 80; ++kl) {
                float b2 = t2s[vk * 81 + kl];
#pragma unroll
                for (int m = 0; m < 5; ++m)
                    acc[m] += t1s[(j * 5 + m) * 81 + kl] * b2;
            }
        }
    }
    if (active) {
        int outb = (ky * (SS * NB) + b) * 625;
#pragma unroll
        for (int m = 0; m < 5; ++m)
            g_partial[outb + (j * 5 + m) * 25 + vk] = acc[m];
    }
}

// ---------------- softmax + A1 ----------------
__global__ void soft_kernel()
{
    const int b = blockIdx.x;
    const int vk = threadIdx.x;
    if (vk >= 25) return;
    const int s = b / NB;
    float r[25];
    float mx = -1e30f;
    for (int vq = 0; vq < 25; ++vq) {
        float sum = 0.f;
        for (int ky = 0; ky < KSPLIT; ++ky)
            sum += g_partial[(ky * (SS * NB) + b) * 625 + vq * 25 + vk];
        r[vq] = sum * (1.f / 4800.f);
        mx = fmaxf(mx, r[vq]);
    }
    float e = 0.f;
    for (int vq = 0; vq < 25; ++vq) { r[vq] = expf(r[vq] - mx); e += r[vq]; }
    float inv = 1.f / e;
    for (int vq = 0; vq < 25; ++vq)
        g_A1[b * 625 + vq * 25 + vk] = g_Afull[s * 625 + vq * 25 + vk] + r[vq] * inv;
}

// ---------------- fused final: stage1 fp32, stage2 tf32 mma ----------------
// smem (u32 units): xs 8192 | ag 64*136 | wt 64*72 | a1s 656
#define AGSTR 136
#define WTSTR 72
#define Z_OFF_AG 8192
#define Z_OFF_WT (8192 + 64 * AGSTR)
#define Z_OFF_A1 (Z_OFF_WT + 64 * WTSTR)
#define Z_SMEM ((Z_OFF_A1 + 656) * 4)

__global__ void __launch_bounds__(256, 2) z_kernel(const float* __restrict__ x,
                                                   float* __restrict__ out)
{
    extern __shared__ uint32_t smz[];
    float* xs = (float*)smz;
    uint32_t* ag = smz + Z_OFF_AG;
    uint32_t* wt = smz + Z_OFF_WT;
    float* a1s = (float*)(smz + Z_OFF_A1);

    const int tid = threadIdx.x;
    const int warp = tid >> 5;
    const int lane = tid & 31;
    const int lr = lane & 3;
    const int lq = lane >> 2;
    const int pb0 = (warp & 3) * 32;   // p block
    const int ob0 = (warp >> 2) * 32;  // o block
    const int t0 = blockIdx.x * 5;
    const int n = blockIdx.y;

    for (int i = tid; i < 8192; i += 256) {
        int c = i >> 7, p = i & 127;
        xs[i] = (p < 125) ? x[(n * CH + c) * TV + t0 * 25 + p] : 0.f;
    }

    float acc[2][4][4];
#pragma unroll
    for (int mi = 0; mi < 2; ++mi)
#pragma unroll
        for (int ni = 0; ni < 4; ++ni)
#pragma unroll
            for (int q = 0; q < 4; ++q) acc[mi][ni][q] = 0.f;

#pragma unroll 1
    for (int s = 0; s < SS; ++s) {
        __syncthreads();   // prev stage2 reads done
        for (int i = tid; i < 4096; i += 256) {
            int c = i >> 6, o = i & 63;
            wt[c * WTSTR + o] = f2tf32(g_WdeT[s * 4096 + i]);
        }
        for (int i = tid; i < 625; i += 256) {
            int vq = i / 25, v = i % 25;
            a1s[vq * 26 + v] = g_A1[(s * NB + n) * 625 + i];
        }
        __syncthreads();
        // stage1: ag[c][p] = sum_u xs[c][tl*25+u] * A1[u][v]  (tf32 store)
        for (int i = tid; i < 8192; i += 256) {
            int c = i >> 7, p = i & 127;
            float sum = 0.f;
            if (p < 125) {
                int tl = p / 25, v = p % 25;
                const float* xr = &xs[(c << 7) + tl * 25];
#pragma unroll
                for (int u = 0; u < 25; ++u)
                    sum += xr[u] * a1s[u * 26 + v];
            }
            ag[c * AGSTR + p] = f2tf32(sum);
        }
        __syncthreads();
        // stage2: D[p][o] += ag^T(p,k) * wt(k,o) via m16n8k8 tf32
#pragma unroll
        for (int kk = 0; kk < 8; ++kk) {
            const int kb = kk * 8;
            uint32_t af[2][4];
#pragma unroll
            for (int mi = 0; mi < 2; ++mi) {
                const uint32_t* p0 = &ag[(kb + lr) * AGSTR + pb0 + mi * 16 + lq];
                af[mi][0] = p0[0];
                af[mi][1] = p0[8];
                af[mi][2] = p0[4 * AGSTR];
                af[mi][3] = p0[4 * AGSTR + 8];
            }
            uint32_t bf[4][2];
#pragma unroll
            for (int ni = 0; ni < 4; ++ni) {
                int ob = ob0 + ni * 8 + lq;
                bf[ni][0] = wt[(kb + lr) * WTSTR + ob];
                bf[ni][1] = wt[(kb + lr + 4) * WTSTR + ob];
            }
#pragma unroll
            for (int mi = 0; mi < 2; ++mi)
#pragma unroll
                for (int ni = 0; ni < 4; ++ni)
                    mma_tf32(acc[mi][ni], af[mi], bf[ni]);
        }
    }

    // epilogue: BN + residual + relu
#pragma unroll
    for (int mi = 0; mi < 2; ++mi) {
#pragma unroll
        for (int ni = 0; ni < 4; ++ni) {
#pragma unroll
            for (int q = 0; q < 4; ++q) {
                int p = pb0 + mi * 16 + lq + (q >> 1) * 8;
                int o = ob0 + ni * 8 + 2 * lr + (q & 1);
                if (p < 125) {
                    float val = fmaf(acc[mi][ni][q] + g_btot[o], g_bnscale[o], g_bnbias[o])
                                + xs[(o << 7) + p];
                    out[(n * CH + o) * TV + t0 * 25 + p] = fmaxf(val, 0.f);
                }
            }
        }
    }
}

// ---------------- launch ----------------
extern "C" void kernel_launch(void* const* d_in, const int* in_sizes, int n_in,
                              void* d_out, int out_size)
{
    const float* x   = (const float*)d_in[0];
    const float* w5  = (const float*)d_in[1];
    const float* A   = (const float*)d_in[2];
    const float* PA  = (const float*)d_in[3];
    const float* Wd  = (const float*)d_in[4];
    const float* bd  = (const float*)d_in[5];
    const float* WT1 = (const float*)d_in[6];
    const float* bT1 = (const float*)d_in[7];
    const float* WT2 = (const float*)d_in[8];
    const float* bT2 = (const float*)d_in[9];
    const float* bng = (const float*)d_in[10];
    const float* bnb = (const float*)d_in[11];
    const float* bnm = (const float*)d_in[12];
    const float* bnv = (const float*)d_in[13];
    float* out = (float*)d_out;

    cudaFuncSetAttribute(tc_conv, cudaFuncAttributeMaxDynamicSharedMemorySize, CONV_SMEM);
    cudaFuncSetAttribute(z_kernel, cudaFuncAttributeMaxDynamicSharedMemorySize, Z_SMEM);

    prep_kernel<<<4, 256>>>(w5, A, PA, Wd, bd, WT1, bT1, WT2, bT2, bng, bnb, bnm, bnv);
    tc_conv<<<dim3(75, NB), 256, CONV_SMEM>>>(x);
    att_kernel<<<dim3(SS * NB, KSPLIT), 128>>>();
    soft_kernel<<<SS * NB, 32>>>();
    z_kernel<<<dim3(60, NB), 256, Z_SMEM>>>(x, out);
}

// round 7
// speedup vs baseline: 2.3894x; 1.0430x over previous
#include <cuda_runtime.h>
#include <stdint.h>

#define NB 64
#define CH 64
#define TT 300
#define VV 25
#define SS 3
#define ICH 16
#define TV 7500
#define KSPLIT 6

// ---------------- scratch ----------------
__device__ float g_T1[SS * NB * ICH * TV];
__device__ float g_T2[SS * NB * ICH * TV];
__device__ __align__(16) uint32_t g_Wb2[9 * 32 * 96];  // [kt][c2][n96] bf16x2
__device__ float g_bT1e[SS * ICH];
__device__ float g_bT2e[SS * ICH];
__device__ float g_WdeT[SS * CH * CH];                 // [s][c][o]
__device__ float g_btot[CH];
__device__ float g_bnscale[CH];
__device__ float g_bnbias[CH];
__device__ float g_Afull[SS * VV * VV];
__device__ float g_partial[KSPLIT * SS * NB * VV * VV];
__device__ float g_A1[SS * NB * VV * VV];

// ---------------- helpers ----------------
__device__ __forceinline__ uint32_t f2tf32(float f) {
    uint32_t r;
    asm("cvt.rna.tf32.f32 %0, %1;" : "=r"(r) : "f"(f));
    return r;
}
__device__ __forceinline__ uint32_t pack_bf16x2(float lo, float hi) {
    uint32_t r;
    asm("cvt.rn.bf16x2.f32 %0, %1, %2;" : "=r"(r) : "f"(hi), "f"(lo));
    return r;
}
__device__ __forceinline__ uint32_t smem_u32(const void* p) {
    uint32_t a;
    asm("{ .reg .u64 t; cvta.to.shared.u64 t, %1; cvt.u32.u64 %0, t; }" : "=r"(a) : "l"(p));
    return a;
}
__device__ __forceinline__ void cp16(uint32_t dst, const void* src) {
    asm volatile("cp.async.cg.shared.global [%0], [%1], 16;" :: "r"(dst), "l"(src));
}
__device__ __forceinline__ void cp_commit() {
    asm volatile("cp.async.commit_group;" ::: "memory");
}
template <int N>
__device__ __forceinline__ void cp_wait() {
    asm volatile("cp.async.wait_group %0;" :: "n"(N) : "memory");
}
__device__ __forceinline__ void mma_bf16(float* c, const uint32_t* a, const uint32_t* b) {
    asm volatile(
        "mma.sync.aligned.m16n8k16.row.col.f32.bf16.bf16.f32 "
        "{%0,%1,%2,%3}, {%4,%5,%6,%7}, {%8,%9}, {%0,%1,%2,%3};"
        : "+f"(c[0]), "+f"(c[1]), "+f"(c[2]), "+f"(c[3])
        : "r"(a[0]), "r"(a[1]), "r"(a[2]), "r"(a[3]), "r"(b[0]), "r"(b[1]));
}
__device__ __forceinline__ void mma_tf32(float* c, const uint32_t* a, const uint32_t* b) {
    asm volatile(
        "mma.sync.aligned.m16n8k8.row.col.f32.tf32.tf32.f32 "
        "{%0,%1,%2,%3}, {%4,%5,%6,%7}, {%8,%9}, {%0,%1,%2,%3};"
        : "+f"(c[0]), "+f"(c[1]), "+f"(c[2]), "+f"(c[3])
        : "r"(a[0]), "r"(a[1]), "r"(a[2]), "r"(a[3]), "r"(b[0]), "r"(b[1]));
}
__device__ __forceinline__ float slim16(int ic, const float* w) {
    if (ic < 9)  return 1.f;
    if (ic < 11) return w[1];
    if (ic < 12) return w[2];
    if (ic < 14) return w[3];
    return w[4];
}
__device__ __forceinline__ float slim64(int o, const float* w) {
    if (o < 38) return 1.f;
    if (o < 44) return w[1];
    if (o < 51) return w[2];
    if (o < 57) return w[3];
    return w[4];
}

// ---------------- prep (split into 3 so tc_conv lands in profiled slot 3) ----
__global__ void prep1_kernel(const float* __restrict__ A, const float* __restrict__ PA)
{
    int tid = threadIdx.x + blockIdx.x * blockDim.x;
    int nt = blockDim.x * gridDim.x;
    for (int i = tid; i < SS * VV * VV; i += nt) {
        float a = A[i];
        float a2 = a * a;
        float ach = 8.f * a2 * a2 - 4.f * a2 - 4.f * a;
        int u = (i / VV) % VV, v = i % VV;
        g_Afull[i] = a + PA[i] + ach + (u == v ? 1.f : 0.f);
    }
}
__global__ void prep2_kernel(const float* __restrict__ w5,
                             const float* __restrict__ WT1, const float* __restrict__ WT2)
{
    int tid = threadIdx.x + blockIdx.x * blockDim.x;
    int nt = blockDim.x * gridDim.x;
    for (int i = tid; i < 9 * 32 * 96; i += nt) {
        int n96 = i % 96;
        int c2 = (i / 96) % 32;
        int kt = i / (96 * 32);
        int s = n96 >> 5;
        int ic2 = n96 & 31;
        int ic = ic2 & 15;
        const float* src = (ic2 < 16) ? WT1 : WT2;
        float sc = slim16(ic, w5);
        float v0 = src[((s * ICH + ic) * CH + 2 * c2) * 9 + kt] * sc;
        float v1 = src[((s * ICH + ic) * CH + 2 * c2 + 1) * 9 + kt] * sc;
        g_Wb2[i] = pack_bf16x2(v0, v1);
    }
}
__global__ void prep3_kernel(const float* __restrict__ w5,
                             const float* __restrict__ Wd, const float* __restrict__ bd,
                             const float* __restrict__ bT1, const float* __restrict__ bT2,
                             const float* __restrict__ bng, const float* __restrict__ bnb,
                             const float* __restrict__ bnm, const float* __restrict__ bnv)
{
    int tid = threadIdx.x + blockIdx.x * blockDim.x;
    int nt = blockDim.x * gridDim.x;
    for (int i = tid; i < SS * ICH; i += nt) {
        int ic = i % ICH;
        float sc = slim16(ic, w5);
        g_bT1e[i] = bT1[i] * sc;
        g_bT2e[i] = bT2[i] * sc;
    }
    for (int i = tid; i < SS * CH * CH; i += nt) {
        int o = i % CH;
        int c = (i / CH) % CH;
        int s = i / (CH * CH);
        g_WdeT[i] = Wd[(s * CH + o) * CH + c] * slim64(o, w5);
    }
    for (int i = tid; i < CH; i += nt) {
        float bt = 0.f;
        for (int s = 0; s < SS; ++s) bt += bd[s * CH + i];
        g_btot[i] = bt * slim64(i, w5);
        float inv = rsqrtf(bnv[i] + 1e-5f);
        float bs = bng[i] * inv;
        g_bnscale[i] = bs;
        g_bnbias[i] = bnb[i] - bnm[i] * bs;
    }
}

// ---------------- bf16 mma conv ----------------
#define XROWS 328
#define XS2_U32 (32 * XROWS)
#define BSTR 104
#define BS2_U32 (32 * BSTR)
#define CONV_SMEM ((XS2_U32 + 2 * BS2_U32) * 4)

__global__ void __launch_bounds__(256, 2) tc_conv(const float* __restrict__ x)
{
    extern __shared__ uint32_t sm[];
    uint32_t* xs = sm;
    uint32_t* bs = sm + XS2_U32;
    const uint32_t bs_addr = smem_u32(sm) + XS2_U32 * 4;

    const int tid = threadIdx.x;
    const int warp = tid >> 5;
    const int lane = tid & 31;
    const int lr = lane & 3;
    const int lq = lane >> 2;
    const int wm = warp & 3;
    const int wn = warp >> 2;
    const int t0 = blockIdx.x * 4;
    const int n = blockIdx.y;

    for (int c2 = warp; c2 < 32; c2 += 8) {
        const float* x0 = x + ((n * CH + 2 * c2) * TT + (t0 - 4)) * VV;
        for (int r = lane; r < XROWS; r += 32) {
            float v0 = 0.f, v1 = 0.f;
            if (r < 300) {
                int t = t0 - 4 + r / 25;
                if (t >= 0 && t < TT) { v0 = x0[r]; v1 = x0[r + TT * VV]; }
            }
            xs[c2 * XROWS + r] = pack_bf16x2(v0, v1);
        }
    }

#pragma unroll
    for (int j = 0; j < 3; ++j) {
        int f = tid + j * 256;
        int c2 = f / 24, off = (f % 24) * 4;
        cp16(bs_addr + (c2 * BSTR + off) * 4, g_Wb2 + c2 * 96 + off);
    }
    cp_commit();

    float acc[2][6][4];
#pragma unroll
    for (int mi = 0; mi < 2; ++mi)
#pragma unroll
        for (int ni = 0; ni < 6; ++ni)
#pragma unroll
            for (int q = 0; q < 4; ++q) acc[mi][ni][q] = 0.f;

#pragma unroll 1
    for (int kt = 0; kt < 9; ++kt) {
        __syncthreads();
        if (kt < 8) {
            const uint32_t dstb = bs_addr + ((kt + 1) & 1) * BS2_U32 * 4;
            const uint32_t* src = g_Wb2 + (kt + 1) * 3072;
#pragma unroll
            for (int j = 0; j < 3; ++j) {
                int f = tid + j * 256;
                int c2 = f / 24, off = (f % 24) * 4;
                cp16(dstb + (c2 * BSTR + off) * 4, src + c2 * 96 + off);
            }
            cp_commit();
            cp_wait<1>();
        } else {
            cp_wait<0>();
        }
        __syncthreads();

        const uint32_t* bsl = bs + (kt & 1) * BS2_U32;
        const int rowoff = kt * 25 + lq;

#pragma unroll
        for (int ks = 0; ks < 4; ++ks) {
            const int kb2 = ks * 8;
            uint32_t af[2][4];
#pragma unroll
            for (int mi = 0; mi < 2; ++mi) {
                int R = wm * 32 + mi * 16 + rowoff;
                const uint32_t* p0 = &xs[(kb2 + lr) * XROWS + R];
                af[mi][0] = p0[0];
                af[mi][1] = p0[8];
                af[mi][2] = p0[4 * XROWS];
                af[mi][3] = p0[4 * XROWS + 8];
            }
            uint32_t bf[6][2];
#pragma unroll
            for (int ni = 0; ni < 6; ++ni) {
                int cb = wn * 48 + ni * 8 + lq;
                bf[ni][0] = bsl[(kb2 + lr) * BSTR + cb];
                bf[ni][1] = bsl[(kb2 + lr + 4) * BSTR + cb];
            }
#pragma unroll
            for (int mi = 0; mi < 2; ++mi)
#pragma unroll
                for (int ni = 0; ni < 6; ++ni)
                    mma_bf16(acc[mi][ni], af[mi], bf[ni]);
        }
    }

#pragma unroll
    for (int mi = 0; mi < 2; ++mi) {
        const int rb = wm * 32 + mi * 16 + lq;
#pragma unroll
        for (int ni = 0; ni < 6; ++ni) {
            const int cb = wn * 48 + ni * 8 + 2 * lr;
#pragma unroll
            for (int q = 0; q < 4; ++q) {
                int row = rb + (q >> 1) * 8;
                int col = cb + (q & 1);
                if (row < 100) {
                    int s = col >> 5;
                    int ic2 = col & 31;
                    int ic = ic2 & 15;
                    float bias, *dst;
                    if (ic2 < 16) { bias = g_bT1e[s * ICH + ic]; dst = g_T1; }
                    else          { bias = g_bT2e[s * ICH + ic]; dst = g_T2; }
                    dst[((s * NB + n) * ICH + ic) * TV + t0 * 25 + row] = acc[mi][ni][q] + bias;
                }
            }
        }
    }
}

// ---------------- attention raw scores: 5x5 register tiles, in-block K-split 5
__global__ void __launch_bounds__(128) att_kernel()
{
    __shared__ float t1s[2000];
    __shared__ float t2s[2000];
    const int tid = threadIdx.x;
    const int b = blockIdx.x;
    const int ky = blockIdx.y;
    const float* p1 = &g_T1[b * (ICH * TV)];
    const float* p2 = &g_T2[b * (ICH * TV)];

    const bool active = tid < 125;
    const int ks = tid / 25;         // K-slice within chunk
    const int tq = (tid % 25) / 5;   // vq tile
    const int tk = tid % 5;          // vk tile

    float acc[5][5];
#pragma unroll
    for (int i = 0; i < 5; ++i)
#pragma unroll
        for (int j = 0; j < 5; ++j) acc[i][j] = 0.f;

    for (int chk = 0; chk < 10; ++chk) {
        int base = (ky * 800 + chk * 80) * 25;
        __syncthreads();
        for (int i = tid; i < 2000; i += 128) {
            t1s[i] = p1[base + i];
            t2s[i] = p2[base + i];
        }
        __syncthreads();
        if (active) {
            const int kb = ks * 16;
#pragma unroll 2
            for (int kl = 0; kl < 16; ++kl) {
                const float* r1 = &t1s[(kb + kl) * 25 + tq * 5];
                const float* r2 = &t2s[(kb + kl) * 25 + tk * 5];
                float t1v[5], t2v[5];
#pragma unroll
                for (int i = 0; i < 5; ++i) t1v[i] = r1[i];
#pragma unroll
                for (int j = 0; j < 5; ++j) t2v[j] = r2[j];
#pragma unroll
                for (int i = 0; i < 5; ++i)
#pragma unroll
                    for (int j = 0; j < 5; ++j)
                        acc[i][j] += t1v[i] * t2v[j];
            }
        }
    }

    // reduce over ks (5) via smem
    float* red = t1s;  // reuse staging (t1s+t2s = 4000 floats >= 3125)
    __syncthreads();
    if (active) {
#pragma unroll
        for (int i = 0; i < 5; ++i)
#pragma unroll
            for (int j = 0; j < 5; ++j)
                red[ks * 625 + (tq * 5 + i) * 25 + tk * 5 + j] = acc[i][j];
    }
    __syncthreads();
    const int outb = (ky * (SS * NB) + b) * 625;
    for (int o = tid; o < 625; o += 128) {
        float s = red[o] + red[625 + o] + red[1250 + o] + red[1875 + o] + red[2500 + o];
        g_partial[outb + o] = s;
    }
}

// ---------------- softmax + A1 ----------------
__global__ void soft_kernel()
{
    const int b = blockIdx.x;
    const int vk = threadIdx.x;
    if (vk >= 25) return;
    const int s = b / NB;
    float r[25];
    float mx = -1e30f;
    for (int vq = 0; vq < 25; ++vq) {
        float sum = 0.f;
        for (int ky = 0; ky < KSPLIT; ++ky)
            sum += g_partial[(ky * (SS * NB) + b) * 625 + vq * 25 + vk];
        r[vq] = sum * (1.f / 4800.f);
        mx = fmaxf(mx, r[vq]);
    }
    float e = 0.f;
    for (int vq = 0; vq < 25; ++vq) { r[vq] = expf(r[vq] - mx); e += r[vq]; }
    float inv = 1.f / e;
    for (int vq = 0; vq < 25; ++vq)
        g_A1[b * 625 + vq * 25 + vk] = g_Afull[s * 625 + vq * 25 + vk] + r[vq] * inv;
}

// ---------------- fused final: stage1 fp32, stage2 tf32 mma ----------------
#define AGSTR 136
#define WTSTR 72
#define Z_OFF_AG 8192
#define Z_OFF_WT (8192 + 64 * AGSTR)
#define Z_OFF_A1 (Z_OFF_WT + 64 * WTSTR)
#define Z_SMEM ((Z_OFF_A1 + 656) * 4)

__global__ void __launch_bounds__(256, 2) z_kernel(const float* __restrict__ x,
                                                   float* __restrict__ out)
{
    extern __shared__ uint32_t smz[];
    float* xs = (float*)smz;
    uint32_t* ag = smz + Z_OFF_AG;
    uint32_t* wt = smz + Z_OFF_WT;
    float* a1s = (float*)(smz + Z_OFF_A1);

    const int tid = threadIdx.x;
    const int warp = tid >> 5;
    const int lane = tid & 31;
    const int lr = lane & 3;
    const int lq = lane >> 2;
    const int pb0 = (warp & 3) * 32;
    const int ob0 = (warp >> 2) * 32;
    const int t0 = blockIdx.x * 5;
    const int n = blockIdx.y;

    for (int i = tid; i < 8192; i += 256) {
        int c = i >> 7, p = i & 127;
        xs[i] = (p < 125) ? x[(n * CH + c) * TV + t0 * 25 + p] : 0.f;
    }

    float acc[2][4][4];
#pragma unroll
    for (int mi = 0; mi < 2; ++mi)
#pragma unroll
        for (int ni = 0; ni < 4; ++ni)
#pragma unroll
            for (int q = 0; q < 4; ++q) acc[mi][ni][q] = 0.f;

#pragma unroll 1
    for (int s = 0; s < SS; ++s) {
        __syncthreads();
        for (int i = tid; i < 4096; i += 256) {
            int c = i >> 6, o = i & 63;
            wt[c * WTSTR + o] = f2tf32(g_WdeT[s * 4096 + i]);
        }
        for (int i = tid; i < 625; i += 256) {
            int vq = i / 25, v = i % 25;
            a1s[vq * 26 + v] = g_A1[(s * NB + n) * 625 + i];
        }
        __syncthreads();
        for (int i = tid; i < 8192; i += 256) {
            int c = i >> 7, p = i & 127;
            float sum = 0.f;
            if (p < 125) {
                int tl = p / 25, v = p % 25;
                const float* xr = &xs[(c << 7) + tl * 25];
#pragma unroll
                for (int u = 0; u < 25; ++u)
                    sum += xr[u] * a1s[u * 26 + v];
            }
            ag[c * AGSTR + p] = f2tf32(sum);
        }
        __syncthreads();
#pragma unroll
        for (int kk = 0; kk < 8; ++kk) {
            const int kb = kk * 8;
            uint32_t af[2][4];
#pragma unroll
            for (int mi = 0; mi < 2; ++mi) {
                const uint32_t* p0 = &ag[(kb + lr) * AGSTR + pb0 + mi * 16 + lq];
                af[mi][0] = p0[0];
                af[mi][1] = p0[8];
                af[mi][2] = p0[4 * AGSTR];
                af[mi][3] = p0[4 * AGSTR + 8];
            }
            uint32_t bf[4][2];
#pragma unroll
            for (int ni = 0; ni < 4; ++ni) {
                int ob = ob0 + ni * 8 + lq;
                bf[ni][0] = wt[(kb + lr) * WTSTR + ob];
                bf[ni][1] = wt[(kb + lr + 4) * WTSTR + ob];
            }
#pragma unroll
            for (int mi = 0; mi < 2; ++mi)
#pragma unroll
                for (int ni = 0; ni < 4; ++ni)
                    mma_tf32(acc[mi][ni], af[mi], bf[ni]);
        }
    }

#pragma unroll
    for (int mi = 0; mi < 2; ++mi) {
#pragma unroll
        for (int ni = 0; ni < 4; ++ni) {
#pragma unroll
            for (int q = 0; q < 4; ++q) {
                int p = pb0 + mi * 16 + lq + (q >> 1) * 8;
                int o = ob0 + ni * 8 + 2 * lr + (q & 1);
                if (p < 125) {
                    float val = fmaf(acc[mi][ni][q] + g_btot[o], g_bnscale[o], g_bnbias[o])
                                + xs[(o << 7) + p];
                    out[(n * CH + o) * TV + t0 * 25 + p] = fmaxf(val, 0.f);
                }
            }
        }
    }
}

// ---------------- launch ----------------
extern "C" void kernel_launch(void* const* d_in, const int* in_sizes, int n_in,
                              void* d_out, int out_size)
{
    const float* x   = (const float*)d_in[0];
    const float* w5  = (const float*)d_in[1];
    const float* A   = (const float*)d_in[2];
    const float* PA  = (const float*)d_in[3];
    const float* Wd  = (const float*)d_in[4];
    const float* bd  = (const float*)d_in[5];
    const float* WT1 = (const float*)d_in[6];
    const float* bT1 = (const float*)d_in[7];
    const float* WT2 = (const float*)d_in[8];
    const float* bT2 = (const float*)d_in[9];
    const float* bng = (const float*)d_in[10];
    const float* bnb = (const float*)d_in[11];
    const float* bnm = (const float*)d_in[12];
    const float* bnv = (const float*)d_in[13];
    float* out = (float*)d_out;

    cudaFuncSetAttribute(tc_conv, cudaFuncAttributeMaxDynamicSharedMemorySize, CONV_SMEM);
    cudaFuncSetAttribute(z_kernel, cudaFuncAttributeMaxDynamicSharedMemorySize, Z_SMEM);

    prep1_kernel<<<2, 256>>>(A, PA);
    prep2_kernel<<<4, 256>>>(w5, WT1, WT2);
    prep3_kernel<<<4, 256>>>(w5, Wd, bd, bT1, bT2, bng, bnb, bnm, bnv);
    tc_conv<<<dim3(75, NB), 256, CONV_SMEM>>>(x);          // profiled slot (index 3)
    att_kernel<<<dim3(SS * NB, KSPLIT), 128>>>();
    soft_kernel<<<SS * NB, 32>>>();
    z_kernel<<<dim3(60, NB), 256, Z_SMEM>>>(x, out);
}

// round 9
// speedup vs baseline: 2.6439x; 1.1065x over previous
#include <cuda_runtime.h>
#include <stdint.h>

#define NB 64
#define CH 64
#define TT 300
#define VV 25
#define SS 3
#define ICH 16
#define TV 7500
#define KSPLIT 6

// ---------------- scratch ----------------
__device__ float g_T1[SS * NB * ICH * TV];
__device__ float g_T2[SS * NB * ICH * TV];
__device__ float g_h[SS * NB * TV * CH + 512];          // [s][n][p][o], tf32 bits
__device__ __align__(16) uint32_t g_Wb2[9 * 32 * 96];   // conv B: [kt][c2][n96] bf16x2
__device__ __align__(16) uint32_t g_Wh[SS * CH * CH];   // [s][c][o] tf32 (slim-scaled)
__device__ float g_bT1e[SS * ICH];
__device__ float g_bT2e[SS * ICH];
__device__ float g_btot[CH];
__device__ float g_bnscale[CH];
__device__ float g_bnbias[CH];
__device__ float g_Afull[SS * VV * VV];
__device__ float g_partial[KSPLIT * SS * NB * VV * VV];
__device__ float g_A1[SS * NB * VV * VV];

// ---------------- helpers ----------------
__device__ __forceinline__ uint32_t f2tf32(float f) {
    uint32_t r;
    asm("cvt.rna.tf32.f32 %0, %1;" : "=r"(r) : "f"(f));
    return r;
}
__device__ __forceinline__ uint32_t pack_bf16x2(float lo, float hi) {
    uint32_t r;
    asm("cvt.rn.bf16x2.f32 %0, %1, %2;" : "=r"(r) : "f"(hi), "f"(lo));
    return r;
}
__device__ __forceinline__ uint32_t smem_u32(const void* p) {
    uint32_t a;
    asm("{ .reg .u64 t; cvta.to.shared.u64 t, %1; cvt.u32.u64 %0, t; }" : "=r"(a) : "l"(p));
    return a;
}
__device__ __forceinline__ void cp16(uint32_t dst, const void* src) {
    asm volatile("cp.async.cg.shared.global [%0], [%1], 16;" :: "r"(dst), "l"(src));
}
__device__ __forceinline__ void cp_commit() {
    asm volatile("cp.async.commit_group;" ::: "memory");
}
template <int N>
__device__ __forceinline__ void cp_wait() {
    asm volatile("cp.async.wait_group %0;" :: "n"(N) : "memory");
}
__device__ __forceinline__ void mma_bf16(float* c, const uint32_t* a, const uint32_t* b) {
    asm volatile(
        "mma.sync.aligned.m16n8k16.row.col.f32.bf16.bf16.f32 "
        "{%0,%1,%2,%3}, {%4,%5,%6,%7}, {%8,%9}, {%0,%1,%2,%3};"
        : "+f"(c[0]), "+f"(c[1]), "+f"(c[2]), "+f"(c[3])
        : "r"(a[0]), "r"(a[1]), "r"(a[2]), "r"(a[3]), "r"(b[0]), "r"(b[1]));
}
__device__ __forceinline__ void mma_tf32(float* c, const uint32_t* a, const uint32_t* b) {
    asm volatile(
        "mma.sync.aligned.m16n8k8.row.col.f32.tf32.tf32.f32 "
        "{%0,%1,%2,%3}, {%4,%5,%6,%7}, {%8,%9}, {%0,%1,%2,%3};"
        : "+f"(c[0]), "+f"(c[1]), "+f"(c[2]), "+f"(c[3])
        : "r"(a[0]), "r"(a[1]), "r"(a[2]), "r"(a[3]), "r"(b[0]), "r"(b[1]));
}
__device__ __forceinline__ float slim16(int ic, const float* w) {
    if (ic < 9)  return 1.f;
    if (ic < 11) return w[1];
    if (ic < 12) return w[2];
    if (ic < 14) return w[3];
    return w[4];
}
__device__ __forceinline__ float slim64(int o, const float* w) {
    if (o < 38) return 1.f;
    if (o < 44) return w[1];
    if (o < 51) return w[2];
    if (o < 57) return w[3];
    return w[4];
}

// ---------------- prep (single kernel, launch index 0) ----------------
__global__ void prep_kernel(const float* __restrict__ w5,
                            const float* __restrict__ A, const float* __restrict__ PA,
                            const float* __restrict__ Wd, const float* __restrict__ bd,
                            const float* __restrict__ WT1, const float* __restrict__ bT1,
                            const float* __restrict__ WT2, const float* __restrict__ bT2,
                            const float* __restrict__ bng, const float* __restrict__ bnb,
                            const float* __restrict__ bnm, const float* __restrict__ bnv)
{
    int tid = threadIdx.x + blockIdx.x * blockDim.x;
    int nt = blockDim.x * gridDim.x;

    for (int i = tid; i < SS * VV * VV; i += nt) {
        float a = A[i];
        float a2 = a * a;
        float ach = 8.f * a2 * a2 - 4.f * a2 - 4.f * a;
        int u = (i / VV) % VV, v = i % VV;
        g_Afull[i] = a + PA[i] + ach + (u == v ? 1.f : 0.f);
    }
    for (int i = tid; i < 9 * 32 * 96; i += nt) {
        int n96 = i % 96;
        int c2 = (i / 96) % 32;
        int kt = i / (96 * 32);
        int s = n96 >> 5;
        int ic2 = n96 & 31;
        int ic = ic2 & 15;
        const float* src = (ic2 < 16) ? WT1 : WT2;
        float sc = slim16(ic, w5);
        float v0 = src[((s * ICH + ic) * CH + 2 * c2) * 9 + kt] * sc;
        float v1 = src[((s * ICH + ic) * CH + 2 * c2 + 1) * 9 + kt] * sc;
        g_Wb2[i] = pack_bf16x2(v0, v1);
    }
    for (int i = tid; i < SS * ICH; i += nt) {
        int ic = i % ICH;
        float sc = slim16(ic, w5);
        g_bT1e[i] = bT1[i] * sc;
        g_bT2e[i] = bT2[i] * sc;
    }
    // W for h_gemm: [s][c][o] tf32, slim-scaled on o
    for (int i = tid; i < SS * CH * CH; i += nt) {
        int o = i & 63;
        int c = (i >> 6) & 63;
        int s = i >> 12;
        g_Wh[i] = f2tf32(Wd[(s * CH + o) * CH + c] * slim64(o, w5));
    }
    for (int i = tid; i < CH; i += nt) {
        float bt = 0.f;
        for (int s = 0; s < SS; ++s) bt += bd[s * CH + i];
        g_btot[i] = bt * slim64(i, w5);
        float inv = rsqrtf(bnv[i] + 1e-5f);
        float bs = bng[i] * inv;
        g_bnscale[i] = bs;
        g_bnbias[i] = bnb[i] - bnm[i] * bs;
    }
}

// ---------------- bf16 mma conv (unchanged, index 1) ----------------
#define XROWS 328
#define XS2_U32 (32 * XROWS)
#define BSTR 104
#define BS2_U32 (32 * BSTR)
#define CONV_SMEM ((XS2_U32 + 2 * BS2_U32) * 4)

__global__ void __launch_bounds__(256, 2) tc_conv(const float* __restrict__ x)
{
    extern __shared__ uint32_t sm[];
    uint32_t* xs = sm;
    uint32_t* bs = sm + XS2_U32;
    const uint32_t bs_addr = smem_u32(sm) + XS2_U32 * 4;

    const int tid = threadIdx.x;
    const int warp = tid >> 5;
    const int lane = tid & 31;
    const int lr = lane & 3;
    const int lq = lane >> 2;
    const int wm = warp & 3;
    const int wn = warp >> 2;
    const int t0 = blockIdx.x * 4;
    const int n = blockIdx.y;

    for (int c2 = warp; c2 < 32; c2 += 8) {
        const float* x0 = x + ((n * CH + 2 * c2) * TT + (t0 - 4)) * VV;
        for (int r = lane; r < XROWS; r += 32) {
            float v0 = 0.f, v1 = 0.f;
            if (r < 300) {
                int t = t0 - 4 + r / 25;
                if (t >= 0 && t < TT) { v0 = x0[r]; v1 = x0[r + TT * VV]; }
            }
            xs[c2 * XROWS + r] = pack_bf16x2(v0, v1);
        }
    }

#pragma unroll
    for (int j = 0; j < 3; ++j) {
        int f = tid + j * 256;
        int c2 = f / 24, off = (f % 24) * 4;
        cp16(bs_addr + (c2 * BSTR + off) * 4, g_Wb2 + c2 * 96 + off);
    }
    cp_commit();

    float acc[2][6][4];
#pragma unroll
    for (int mi = 0; mi < 2; ++mi)
#pragma unroll
        for (int ni = 0; ni < 6; ++ni)
#pragma unroll
            for (int q = 0; q < 4; ++q) acc[mi][ni][q] = 0.f;

#pragma unroll 1
    for (int kt = 0; kt < 9; ++kt) {
        __syncthreads();
        if (kt < 8) {
            const uint32_t dstb = bs_addr + ((kt + 1) & 1) * BS2_U32 * 4;
            const uint32_t* src = g_Wb2 + (kt + 1) * 3072;
#pragma unroll
            for (int j = 0; j < 3; ++j) {
                int f = tid + j * 256;
                int c2 = f / 24, off = (f % 24) * 4;
                cp16(dstb + (c2 * BSTR + off) * 4, src + c2 * 96 + off);
            }
            cp_commit();
            cp_wait<1>();
        } else {
            cp_wait<0>();
        }
        __syncthreads();

        const uint32_t* bsl = bs + (kt & 1) * BS2_U32;
        const int rowoff = kt * 25 + lq;

#pragma unroll
        for (int ks = 0; ks < 4; ++ks) {
            const int kb2 = ks * 8;
            uint32_t af[2][4];
#pragma unroll
            for (int mi = 0; mi < 2; ++mi) {
                int R = wm * 32 + mi * 16 + rowoff;
                const uint32_t* p0 = &xs[(kb2 + lr) * XROWS + R];
                af[mi][0] = p0[0];
                af[mi][1] = p0[8];
                af[mi][2] = p0[4 * XROWS];
                af[mi][3] = p0[4 * XROWS + 8];
            }
            uint32_t bf[6][2];
#pragma unroll
            for (int ni = 0; ni < 6; ++ni) {
                int cb = wn * 48 + ni * 8 + lq;
                bf[ni][0] = bsl[(kb2 + lr) * BSTR + cb];
                bf[ni][1] = bsl[(kb2 + lr + 4) * BSTR + cb];
            }
#pragma unroll
            for (int mi = 0; mi < 2; ++mi)
#pragma unroll
                for (int ni = 0; ni < 6; ++ni)
                    mma_bf16(acc[mi][ni], af[mi], bf[ni]);
        }
    }

#pragma unroll
    for (int mi = 0; mi < 2; ++mi) {
        const int rb = wm * 32 + mi * 16 + lq;
#pragma unroll
        for (int ni = 0; ni < 6; ++ni) {
            const int cb = wn * 48 + ni * 8 + 2 * lr;
#pragma unroll
            for (int q = 0; q < 4; ++q) {
                int row = rb + (q >> 1) * 8;
                int col = cb + (q & 1);
                if (row < 100) {
                    int s = col >> 5;
                    int ic2 = col & 31;
                    int ic = ic2 & 15;
                    float bias, *dst;
                    if (ic2 < 16) { bias = g_bT1e[s * ICH + ic]; dst = g_T1; }
                    else          { bias = g_bT2e[s * ICH + ic]; dst = g_T2; }
                    dst[((s * NB + n) * ICH + ic) * TV + t0 * 25 + row] = acc[mi][ni][q] + bias;
                }
            }
        }
    }
}

// ---------------- h = Wd_eff . x  (tf32 mma, index 2) ----------------
// CTA = (p-tile 125, n). D[128p x 64o], K=64c, loop s. h layout [s][n][p][o].
#define HG_XB_STR 132
#define HG_XB (64 * HG_XB_STR)          // 8448
#define HG_WB_STR 68
#define HG_WB (64 * HG_WB_STR)          // 4352
#define HG_D_STR 65
#define HG_D (128 * HG_D_STR)           // 8320
#define HG_SMEM ((HG_XB + HG_WB + HG_D) * 4)

__global__ void __launch_bounds__(256, 2) h_gemm(const float* __restrict__ x)
{
    extern __shared__ uint32_t smh[];
    uint32_t* xB = smh;                  // [c][p] tf32 (K-major for rows p)
    uint32_t* wB = smh + HG_XB;          // [c][o] tf32
    float* Dbuf = (float*)(smh + HG_XB + HG_WB);

    const int tid = threadIdx.x;
    const int warp = tid >> 5;
    const int lane = tid & 31;
    const int lr = lane & 3;
    const int lq = lane >> 2;
    const int p0 = blockIdx.x * 125;
    const int n = blockIdx.y;

    // stage x tile once
    for (int i = tid; i < HG_XB; i += 256) {
        int c = i / HG_XB_STR, p = i % HG_XB_STR;
        xB[i] = (p < 125) ? f2tf32(x[(n * CH + c) * TV + p0 + p]) : 0u;
    }

#pragma unroll 1
    for (int s = 0; s < SS; ++s) {
        // stage W[s]
        for (int i = tid; i < 4096; i += 256) {
            int c = i >> 6, o = i & 63;
            wB[c * HG_WB_STR + o] = g_Wh[s * 4096 + i];
        }
        __syncthreads();

        float acc[8][4];
#pragma unroll
        for (int ni = 0; ni < 8; ++ni)
#pragma unroll
            for (int q = 0; q < 4; ++q) acc[ni][q] = 0.f;

#pragma unroll
        for (int kk = 0; kk < 8; ++kk) {
            const int kb = kk * 8;
            uint32_t af[4];
            {
                const uint32_t* pA = &xB[(kb + lr) * HG_XB_STR + warp * 16 + lq];
                af[0] = pA[0];
                af[1] = pA[8];
                af[2] = pA[4 * HG_XB_STR];
                af[3] = pA[4 * HG_XB_STR + 8];
            }
#pragma unroll
            for (int ni = 0; ni < 8; ++ni) {
                uint32_t bf[2];
                const uint32_t* pB = &wB[(kb + lr) * HG_WB_STR + ni * 8 + lq];
                bf[0] = pB[0];
                bf[1] = pB[4 * HG_WB_STR];
                mma_tf32(acc[ni], af, bf);
            }
        }

        // bounce D through smem for coalesced store
#pragma unroll
        for (int ni = 0; ni < 8; ++ni)
#pragma unroll
            for (int q = 0; q < 4; ++q) {
                int pr = warp * 16 + lq + (q >> 1) * 8;
                int o = ni * 8 + 2 * lr + (q & 1);
                Dbuf[pr * HG_D_STR + o] = acc[ni][q];
            }
        __syncthreads();
        {
            float* hdst = g_h + ((s * NB + n) * TV + p0) * CH;
            for (int i = tid; i < 8000; i += 256) {
                int p = i >> 6, o = i & 63;
                hdst[i] = __uint_as_float(f2tf32(Dbuf[p * HG_D_STR + o]));
            }
        }
        // next s: wB restage + Dbuf reuse both guarded by the loop-top sync
        __syncthreads();
    }
}

// ---------------- attention raw scores (index 3: profiled) ----------------
__global__ void __launch_bounds__(128) att_kernel()
{
    __shared__ float t1s[2000];
    __shared__ float t2s[2000];
    const int tid = threadIdx.x;
    const int b = blockIdx.x;
    const int ky = blockIdx.y;
    const float* p1 = &g_T1[b * (ICH * TV)];
    const float* p2 = &g_T2[b * (ICH * TV)];

    const bool active = tid < 125;
    const int ks = tid / 25;
    const int tq = (tid % 25) / 5;
    const int tk = tid % 5;

    float acc[5][5];
#pragma unroll
    for (int i = 0; i < 5; ++i)
#pragma unroll
        for (int j = 0; j < 5; ++j) acc[i][j] = 0.f;

    for (int chk = 0; chk < 10; ++chk) {
        int base = (ky * 800 + chk * 80) * 25;
        __syncthreads();
        for (int i = tid; i < 2000; i += 128) {
            t1s[i] = p1[base + i];
            t2s[i] = p2[base + i];
        }
        __syncthreads();
        if (active) {
            const int kb = ks * 16;
#pragma unroll 2
            for (int kl = 0; kl < 16; ++kl) {
                const float* r1 = &t1s[(kb + kl) * 25 + tq * 5];
                const float* r2 = &t2s[(kb + kl) * 25 + tk * 5];
                float t1v[5], t2v[5];
#pragma unroll
                for (int i = 0; i < 5; ++i) t1v[i] = r1[i];
#pragma unroll
                for (int j = 0; j < 5; ++j) t2v[j] = r2[j];
#pragma unroll
                for (int i = 0; i < 5; ++i)
#pragma unroll
                    for (int j = 0; j < 5; ++j)
                        acc[i][j] += t1v[i] * t2v[j];
            }
        }
    }

    float* red = t1s;
    __syncthreads();
    if (active) {
#pragma unroll
        for (int i = 0; i < 5; ++i)
#pragma unroll
            for (int j = 0; j < 5; ++j)
                red[ks * 625 + (tq * 5 + i) * 25 + tk * 5 + j] = acc[i][j];
    }
    __syncthreads();
    const int outb = (ky * (SS * NB) + b) * 625;
    for (int o = tid; o < 625; o += 128) {
        float s = red[o] + red[625 + o] + red[1250 + o] + red[1875 + o] + red[2500 + o];
        g_partial[outb + o] = s;
    }
}

// ---------------- softmax + A1 (index 4) ----------------
__global__ void soft_kernel()
{
    const int b = blockIdx.x;
    const int vk = threadIdx.x;
    if (vk >= 25) return;
    const int s = b / NB;
    float r[25];
    float mx = -1e30f;
    for (int vq = 0; vq < 25; ++vq) {
        float sum = 0.f;
        for (int ky = 0; ky < KSPLIT; ++ky)
            sum += g_partial[(ky * (SS * NB) + b) * 625 + vq * 25 + vk];
        r[vq] = sum * (1.f / 4800.f);
        mx = fmaxf(mx, r[vq]);
    }
    float e = 0.f;
    for (int vq = 0; vq < 25; ++vq) { r[vq] = expf(r[vq] - mx); e += r[vq]; }
    float inv = 1.f / e;
    for (int vq = 0; vq < 25; ++vq)
        g_A1[b * 625 + vq * 25 + vk] = g_Afull[s * 625 + vq * 25 + vk] + r[vq] * inv;
}

// ---------------- z2: z = sum_s h_s . A1_s, BN + residual + relu (index 5) --
// CTA = (4-t tile, n). rows r = tl*64+o (256), N = 32 (v pad), K = 32 (u pad) x 3s.
#define Z2_HS_STR 260
#define Z2_HS (32 * Z2_HS_STR)          // 8320: hs[u][r]
#define Z2_A1_STR 36
#define Z2_A1S 1152                      // 32*36 per s
#define Z2_SMEM ((Z2_HS + 3 * Z2_A1S) * 4)

__global__ void __launch_bounds__(256, 3) z2_kernel(const float* __restrict__ x,
                                                    float* __restrict__ out)
{
    extern __shared__ uint32_t smz[];
    uint32_t* hs = smz;                       // [u][r=tl*64+o]
    uint32_t* a1t = smz + Z2_HS;              // [s][v][u] tf32

    const int tid = threadIdx.x;
    const int warp = tid >> 5;
    const int lane = tid & 31;
    const int lr = lane & 3;
    const int lq = lane >> 2;
    const int t0 = blockIdx.x * 4;
    const int n = blockIdx.y;
    const int p0 = t0 * 25;

    // stage A1^T (all 3 s) once
    for (int i = tid; i < 3 * 1024; i += 256) {
        int s = i >> 10;
        int v = (i >> 5) & 31;
        int u = i & 31;
        uint32_t val = 0u;
        if (v < VV && u < VV)
            val = f2tf32(g_A1[(s * NB + n) * 625 + u * 25 + v]);
        a1t[s * Z2_A1S + v * Z2_A1_STR + u] = val;
    }

    float acc[2][4][4];
#pragma unroll
    for (int mi = 0; mi < 2; ++mi)
#pragma unroll
        for (int ni = 0; ni < 4; ++ni)
#pragma unroll
            for (int q = 0; q < 4; ++q) acc[mi][ni][q] = 0.f;

#pragma unroll 1
    for (int s = 0; s < SS; ++s) {
        __syncthreads();
        // stage h tile: rows (tl,o), k = u (25 real + 7 pad-read, killed by a1t zeros)
        {
            const float* hsrc = g_h + ((s * NB + n) * TV + p0) * CH;
            for (int i = tid; i < 8192; i += 256) {
                int o = i & 63;
                int slot = i >> 6;            // tl*32 + u
                int tl = slot >> 5, u = slot & 31;
                hs[u * Z2_HS_STR + tl * 64 + o] =
                    __float_as_uint(hsrc[(tl * 25 + u) * CH + o]);
            }
        }
        __syncthreads();

#pragma unroll
        for (int kk = 0; kk < 4; ++kk) {
            const int kb = kk * 8;
            uint32_t af[2][4];
#pragma unroll
            for (int mi = 0; mi < 2; ++mi) {
                const uint32_t* pA = &hs[(kb + lr) * Z2_HS_STR + warp * 32 + mi * 16 + lq];
                af[mi][0] = pA[0];
                af[mi][1] = pA[8];
                af[mi][2] = pA[4 * Z2_HS_STR];
                af[mi][3] = pA[4 * Z2_HS_STR + 8];
            }
            uint32_t bf[4][2];
#pragma unroll
            for (int ni = 0; ni < 4; ++ni) {
                const uint32_t* pB = &a1t[s * Z2_A1S + (ni * 8 + lq) * Z2_A1_STR + kb + lr];
                bf[ni][0] = pB[0];
                bf[ni][1] = pB[4];
            }
#pragma unroll
            for (int mi = 0; mi < 2; ++mi)
#pragma unroll
                for (int ni = 0; ni < 4; ++ni)
                    mma_tf32(acc[mi][ni], af[mi], bf[ni]);
        }
    }

    // epilogue: BN + residual + relu
#pragma unroll
    for (int mi = 0; mi < 2; ++mi) {
#pragma unroll
        for (int ni = 0; ni < 4; ++ni) {
#pragma unroll
            for (int q = 0; q < 4; ++q) {
                int r = warp * 32 + mi * 16 + lq + (q >> 1) * 8;
                int v = ni * 8 + 2 * lr + (q & 1);
                if (v < VV) {
                    int tl = r >> 6, o = r & 63;
                    int gi = ((n * CH + o) * TT + t0 + tl) * VV + v;
                    float val = fmaf(acc[mi][ni][q] + g_btot[o], g_bnscale[o], g_bnbias[o])
                                + x[gi];
                    out[gi] = fmaxf(val, 0.f);
                }
            }
        }
    }
}

// ---------------- launch ----------------
extern "C" void kernel_launch(void* const* d_in, const int* in_sizes, int n_in,
                              void* d_out, int out_size)
{
    const float* x   = (const float*)d_in[0];
    const float* w5  = (const float*)d_in[1];
    const float* A   = (const float*)d_in[2];
    const float* PA  = (const float*)d_in[3];
    const float* Wd  = (const float*)d_in[4];
    const float* bd  = (const float*)d_in[5];
    const float* WT1 = (const float*)d_in[6];
    const float* bT1 = (const float*)d_in[7];
    const float* WT2 = (const float*)d_in[8];
    const float* bT2 = (const float*)d_in[9];
    const float* bng = (const float*)d_in[10];
    const float* bnb = (const float*)d_in[11];
    const float* bnm = (const float*)d_in[12];
    const float* bnv = (const float*)d_in[13];
    float* out = (float*)d_out;

    cudaFuncSetAttribute(tc_conv,  cudaFuncAttributeMaxDynamicSharedMemorySize, CONV_SMEM);
    cudaFuncSetAttribute(h_gemm,   cudaFuncAttributeMaxDynamicSharedMemorySize, HG_SMEM);
    cudaFuncSetAttribute(z2_kernel, cudaFuncAttributeMaxDynamicSharedMemorySize, Z2_SMEM);

    prep_kernel<<<4, 256>>>(w5, A, PA, Wd, bd, WT1, bT1, WT2, bT2, bng, bnb, bnm, bnv);
    tc_conv<<<dim3(75, NB), 256, CONV_SMEM>>>(x);
    h_gemm<<<dim3(60, NB), 256, HG_SMEM>>>(x);
    att_kernel<<<dim3(SS * NB, KSPLIT), 128>>>();   // profiled slot (index 3)
    soft_kernel<<<SS * NB, 32>>>();
    z2_kernel<<<dim3(75, NB), 256, Z2_SMEM>>>(x, out);
}

// round 11
// speedup vs baseline: 3.1902x; 1.2066x over previous
#include <cuda_runtime.h>
#include <stdint.h>

#define NB 64
#define CH 64
#define TT 300
#define VV 25
#define SS 3
#define ICH 16
#define TV 7500
#define KSPLIT 6

// ---------------- scratch ----------------
__device__ float g_T1[SS * NB * ICH * TV];
__device__ float g_T2[SS * NB * ICH * TV];
__device__ __align__(16) uint32_t g_Wb2[9 * 32 * 96];   // conv B: [kt][c2][n96] bf16x2
__device__ __align__(16) uint32_t g_Wh[SS * CH * CH];   // [s][c][o] tf32 (slim-scaled)
__device__ float g_bT1e[SS * ICH];
__device__ float g_bT2e[SS * ICH];
__device__ float g_btot[CH];
__device__ float g_bnscale[CH];
__device__ float g_bnbias[CH];
__device__ float g_Afull[SS * VV * VV];
__device__ float g_partial[KSPLIT * SS * NB * VV * VV];
__device__ float g_A1[SS * NB * VV * VV];

// ---------------- helpers ----------------
__device__ __forceinline__ uint32_t f2tf32(float f) {
    uint32_t r;
    asm("cvt.rna.tf32.f32 %0, %1;" : "=r"(r) : "f"(f));
    return r;
}
__device__ __forceinline__ uint32_t pack_bf16x2(float lo, float hi) {
    uint32_t r;
    asm("cvt.rn.bf16x2.f32 %0, %1, %2;" : "=r"(r) : "f"(hi), "f"(lo));
    return r;
}
__device__ __forceinline__ uint32_t smem_u32(const void* p) {
    uint32_t a;
    asm("{ .reg .u64 t; cvta.to.shared.u64 t, %1; cvt.u32.u64 %0, t; }" : "=r"(a) : "l"(p));
    return a;
}
__device__ __forceinline__ void cp16(uint32_t dst, const void* src) {
    asm volatile("cp.async.cg.shared.global [%0], [%1], 16;" :: "r"(dst), "l"(src));
}
__device__ __forceinline__ void cp_commit() {
    asm volatile("cp.async.commit_group;" ::: "memory");
}
template <int N>
__device__ __forceinline__ void cp_wait() {
    asm volatile("cp.async.wait_group %0;" :: "n"(N) : "memory");
}
__device__ __forceinline__ void mma_bf16(float* c, const uint32_t* a, const uint32_t* b) {
    asm volatile(
        "mma.sync.aligned.m16n8k16.row.col.f32.bf16.bf16.f32 "
        "{%0,%1,%2,%3}, {%4,%5,%6,%7}, {%8,%9}, {%0,%1,%2,%3};"
        : "+f"(c[0]), "+f"(c[1]), "+f"(c[2]), "+f"(c[3])
        : "r"(a[0]), "r"(a[1]), "r"(a[2]), "r"(a[3]), "r"(b[0]), "r"(b[1]));
}
__device__ __forceinline__ void mma_tf32(float* c, const uint32_t* a, const uint32_t* b) {
    asm volatile(
        "mma.sync.aligned.m16n8k8.row.col.f32.tf32.tf32.f32 "
        "{%0,%1,%2,%3}, {%4,%5,%6,%7}, {%8,%9}, {%0,%1,%2,%3};"
        : "+f"(c[0]), "+f"(c[1]), "+f"(c[2]), "+f"(c[3])
        : "r"(a[0]), "r"(a[1]), "r"(a[2]), "r"(a[3]), "r"(b[0]), "r"(b[1]));
}
__device__ __forceinline__ float slim16(int ic, const float* w) {
    if (ic < 9)  return 1.f;
    if (ic < 11) return w[1];
    if (ic < 12) return w[2];
    if (ic < 14) return w[3];
    return w[4];
}
__device__ __forceinline__ float slim64(int o, const float* w) {
    if (o < 38) return 1.f;
    if (o < 44) return w[1];
    if (o < 51) return w[2];
    if (o < 57) return w[3];
    return w[4];
}

// ---------------- prep split (indices 0..2 so conv lands in slot 3) --------
__global__ void prep1_kernel(const float* __restrict__ A, const float* __restrict__ PA)
{
    int tid = threadIdx.x + blockIdx.x * blockDim.x;
    int nt = blockDim.x * gridDim.x;
    for (int i = tid; i < SS * VV * VV; i += nt) {
        float a = A[i];
        float a2 = a * a;
        float ach = 8.f * a2 * a2 - 4.f * a2 - 4.f * a;
        int u = (i / VV) % VV, v = i % VV;
        g_Afull[i] = a + PA[i] + ach + (u == v ? 1.f : 0.f);
    }
}
__global__ void prep2_kernel(const float* __restrict__ w5,
                             const float* __restrict__ WT1, const float* __restrict__ WT2)
{
    int tid = threadIdx.x + blockIdx.x * blockDim.x;
    int nt = blockDim.x * gridDim.x;
    for (int i = tid; i < 9 * 32 * 96; i += nt) {
        int n96 = i % 96;
        int c2 = (i / 96) % 32;
        int kt = i / (96 * 32);
        int s = n96 >> 5;
        int ic2 = n96 & 31;
        int ic = ic2 & 15;
        const float* src = (ic2 < 16) ? WT1 : WT2;
        float sc = slim16(ic, w5);
        float v0 = src[((s * ICH + ic) * CH + 2 * c2) * 9 + kt] * sc;
        float v1 = src[((s * ICH + ic) * CH + 2 * c2 + 1) * 9 + kt] * sc;
        g_Wb2[i] = pack_bf16x2(v0, v1);
    }
}
__global__ void prep3_kernel(const float* __restrict__ w5,
                             const float* __restrict__ Wd, const float* __restrict__ bd,
                             const float* __restrict__ bT1, const float* __restrict__ bT2,
                             const float* __restrict__ bng, const float* __restrict__ bnb,
                             const float* __restrict__ bnm, const float* __restrict__ bnv)
{
    int tid = threadIdx.x + blockIdx.x * blockDim.x;
    int nt = blockDim.x * gridDim.x;
    for (int i = tid; i < SS * ICH; i += nt) {
        int ic = i % ICH;
        float sc = slim16(ic, w5);
        g_bT1e[i] = bT1[i] * sc;
        g_bT2e[i] = bT2[i] * sc;
    }
    for (int i = tid; i < SS * CH * CH; i += nt) {
        int o = i & 63;
        int c = (i >> 6) & 63;
        int s = i >> 12;
        g_Wh[i] = f2tf32(Wd[(s * CH + o) * CH + c] * slim64(o, w5));
    }
    for (int i = tid; i < CH; i += nt) {
        float bt = 0.f;
        for (int s = 0; s < SS; ++s) bt += bd[s * CH + i];
        g_btot[i] = bt * slim64(i, w5);
        float inv = rsqrtf(bnv[i] + 1e-5f);
        float bs = bng[i] * inv;
        g_bnscale[i] = bs;
        g_bnbias[i] = bnb[i] - bnm[i] * bs;
    }
}

// ---------------- bf16 mma conv (index 3: profiled) ----------------
#define XROWS 328
#define XS2_U32 (32 * XROWS)
#define BSTR 104
#define BS2_U32 (32 * BSTR)
#define CONV_SMEM ((XS2_U32 + 2 * BS2_U32) * 4)

__global__ void __launch_bounds__(256, 2) tc_conv(const float* __restrict__ x)
{
    extern __shared__ uint32_t sm[];
    uint32_t* xs = sm;
    uint32_t* bs = sm + XS2_U32;
    const uint32_t bs_addr = smem_u32(sm) + XS2_U32 * 4;

    const int tid = threadIdx.x;
    const int warp = tid >> 5;
    const int lane = tid & 31;
    const int lr = lane & 3;
    const int lq = lane >> 2;
    const int wm = warp & 3;
    const int wn = warp >> 2;
    const int t0 = blockIdx.x * 4;
    const int n = blockIdx.y;

    for (int c2 = warp; c2 < 32; c2 += 8) {
        const float* x0 = x + ((n * CH + 2 * c2) * TT + (t0 - 4)) * VV;
        for (int r = lane; r < XROWS; r += 32) {
            float v0 = 0.f, v1 = 0.f;
            if (r < 300) {
                int t = t0 - 4 + r / 25;
                if (t >= 0 && t < TT) { v0 = x0[r]; v1 = x0[r + TT * VV]; }
            }
            xs[c2 * XROWS + r] = pack_bf16x2(v0, v1);
        }
    }

#pragma unroll
    for (int j = 0; j < 3; ++j) {
        int f = tid + j * 256;
        int c2 = f / 24, off = (f % 24) * 4;
        cp16(bs_addr + (c2 * BSTR + off) * 4, g_Wb2 + c2 * 96 + off);
    }
    cp_commit();

    float acc[2][6][4];
#pragma unroll
    for (int mi = 0; mi < 2; ++mi)
#pragma unroll
        for (int ni = 0; ni < 6; ++ni)
#pragma unroll
            for (int q = 0; q < 4; ++q) acc[mi][ni][q] = 0.f;

#pragma unroll 1
    for (int kt = 0; kt < 9; ++kt) {
        __syncthreads();
        if (kt < 8) {
            const uint32_t dstb = bs_addr + ((kt + 1) & 1) * BS2_U32 * 4;
            const uint32_t* src = g_Wb2 + (kt + 1) * 3072;
#pragma unroll
            for (int j = 0; j < 3; ++j) {
                int f = tid + j * 256;
                int c2 = f / 24, off = (f % 24) * 4;
                cp16(dstb + (c2 * BSTR + off) * 4, src + c2 * 96 + off);
            }
            cp_commit();
            cp_wait<1>();
        } else {
            cp_wait<0>();
        }
        __syncthreads();

        const uint32_t* bsl = bs + (kt & 1) * BS2_U32;
        const int rowoff = kt * 25 + lq;

#pragma unroll
        for (int ks = 0; ks < 4; ++ks) {
            const int kb2 = ks * 8;
            uint32_t af[2][4];
#pragma unroll
            for (int mi = 0; mi < 2; ++mi) {
                int R = wm * 32 + mi * 16 + rowoff;
                const uint32_t* p0 = &xs[(kb2 + lr) * XROWS + R];
                af[mi][0] = p0[0];
                af[mi][1] = p0[8];
                af[mi][2] = p0[4 * XROWS];
                af[mi][3] = p0[4 * XROWS + 8];
            }
            uint32_t bf[6][2];
#pragma unroll
            for (int ni = 0; ni < 6; ++ni) {
                int cb = wn * 48 + ni * 8 + lq;
                bf[ni][0] = bsl[(kb2 + lr) * BSTR + cb];
                bf[ni][1] = bsl[(kb2 + lr + 4) * BSTR + cb];
            }
#pragma unroll
            for (int mi = 0; mi < 2; ++mi)
#pragma unroll
                for (int ni = 0; ni < 6; ++ni)
                    mma_bf16(acc[mi][ni], af[mi], bf[ni]);
        }
    }

#pragma unroll
    for (int mi = 0; mi < 2; ++mi) {
        const int rb = wm * 32 + mi * 16 + lq;
#pragma unroll
        for (int ni = 0; ni < 6; ++ni) {
            const int cb = wn * 48 + ni * 8 + 2 * lr;
#pragma unroll
            for (int q = 0; q < 4; ++q) {
                int row = rb + (q >> 1) * 8;
                int col = cb + (q & 1);
                if (row < 100) {
                    int s = col >> 5;
                    int ic2 = col & 31;
                    int ic = ic2 & 15;
                    float bias, *dst;
                    if (ic2 < 16) { bias = g_bT1e[s * ICH + ic]; dst = g_T1; }
                    else          { bias = g_bT2e[s * ICH + ic]; dst = g_T2; }
                    dst[((s * NB + n) * ICH + ic) * TV + t0 * 25 + row] = acc[mi][ni][q] + bias;
                }
            }
        }
    }
}

// ---------------- attention raw scores (index 4) ----------------
__global__ void __launch_bounds__(128) att_kernel()
{
    __shared__ float t1s[2000];
    __shared__ float t2s[2000];
    const int tid = threadIdx.x;
    const int b = blockIdx.x;
    const int ky = blockIdx.y;
    const float* p1 = &g_T1[b * (ICH * TV)];
    const float* p2 = &g_T2[b * (ICH * TV)];

    const bool active = tid < 125;
    const int ks = tid / 25;
    const int tq = (tid % 25) / 5;
    const int tk = tid % 5;

    float acc[5][5];
#pragma unroll
    for (int i = 0; i < 5; ++i)
#pragma unroll
        for (int j = 0; j < 5; ++j) acc[i][j] = 0.f;

    for (int chk = 0; chk < 10; ++chk) {
        int base = (ky * 800 + chk * 80) * 25;
        __syncthreads();
        for (int i = tid; i < 2000; i += 128) {
            t1s[i] = p1[base + i];
            t2s[i] = p2[base + i];
        }
        __syncthreads();
        if (active) {
            const int kb = ks * 16;
#pragma unroll 2
            for (int kl = 0; kl < 16; ++kl) {
                const float* r1 = &t1s[(kb + kl) * 25 + tq * 5];
                const float* r2 = &t2s[(kb + kl) * 25 + tk * 5];
                float t1v[5], t2v[5];
#pragma unroll
                for (int i = 0; i < 5; ++i) t1v[i] = r1[i];
#pragma unroll
                for (int j = 0; j < 5; ++j) t2v[j] = r2[j];
#pragma unroll
                for (int i = 0; i < 5; ++i)
#pragma unroll
                    for (int j = 0; j < 5; ++j)
                        acc[i][j] += t1v[i] * t2v[j];
            }
        }
    }

    float* red = t1s;
    __syncthreads();
    if (active) {
#pragma unroll
        for (int i = 0; i < 5; ++i)
#pragma unroll
            for (int j = 0; j < 5; ++j)
                red[ks * 625 + (tq * 5 + i) * 25 + tk * 5 + j] = acc[i][j];
    }
    __syncthreads();
    const int outb = (ky * (SS * NB) + b) * 625;
    for (int o = tid; o < 625; o += 128) {
        float s = red[o] + red[625 + o] + red[1250 + o] + red[1875 + o] + red[2500 + o];
        g_partial[outb + o] = s;
    }
}

// ---------------- softmax + A1 (index 5) ----------------
__global__ void soft_kernel()
{
    const int b = blockIdx.x;
    const int vk = threadIdx.x;
    if (vk >= 25) return;
    const int s = b / NB;
    float r[25];
    float mx = -1e30f;
    for (int vq = 0; vq < 25; ++vq) {
        float sum = 0.f;
        for (int ky = 0; ky < KSPLIT; ++ky)
            sum += g_partial[(ky * (SS * NB) + b) * 625 + vq * 25 + vk];
        r[vq] = sum * (1.f / 4800.f);
        mx = fmaxf(mx, r[vq]);
    }
    float e = 0.f;
    for (int vq = 0; vq < 25; ++vq) { r[vq] = expf(r[vq] - mx); e += r[vq]; }
    float inv = 1.f / e;
    for (int vq = 0; vq < 25; ++vq)
        g_A1[b * 625 + vq * 25 + vk] = g_Afull[s * 625 + vq * 25 + vk] + r[vq] * inv;
}

// ---------------- fused z: h = W.x in smem, z = sum_s h.A1_s (index 6) -----
// CTA = (4-t tile = 100 pos, n), 256 threads.
// stage1: D1[p128 x o64] = xB[c][p]^T(K-major) . wB[c][o], K=64
// stage2: D2[r=(tl,o) 256 x v32] += hs[u][r]^T . a1t[v][u], K=32, over s
#define FZ_XB_STR 104
#define FZ_XB (64 * FZ_XB_STR)           // 6656
#define FZ_WB_STR 68
#define FZ_WB (64 * FZ_WB_STR)           // 4352
#define FZ_HS_STR 260
#define FZ_HS (32 * FZ_HS_STR)           // 8320
#define FZ_A1_STR 36
#define FZ_A1S (32 * FZ_A1_STR)          // 1152 per s
#define FZ_SMEM ((FZ_XB + FZ_WB + FZ_HS + 3 * FZ_A1S) * 4)

__global__ void __launch_bounds__(256, 2) fz_kernel(const float* __restrict__ x,
                                                    float* __restrict__ out)
{
    extern __shared__ uint32_t smz[];
    uint32_t* xB  = smz;                         // [c][p] tf32
    uint32_t* wB  = smz + FZ_XB;                 // [c][o] tf32
    uint32_t* hs  = smz + FZ_XB + FZ_WB;         // [u][tl*64+o] tf32
    uint32_t* a1t = smz + FZ_XB + FZ_WB + FZ_HS; // [s][v][u] tf32

    const int tid = threadIdx.x;
    const int warp = tid >> 5;
    const int lane = tid & 31;
    const int lr = lane & 3;
    const int lq = lane >> 2;
    const int t0 = blockIdx.x * 4;
    const int p0 = t0 * 25;
    const int n = blockIdx.y;

    // stage x tile [c][p] (p0..p0+99, pad to 104)
    for (int i = tid; i < FZ_XB; i += 256) {
        int c = i / FZ_XB_STR, p = i % FZ_XB_STR;
        xB[i] = (p < 100) ? f2tf32(x[(n * CH + c) * TV + p0 + p]) : 0u;
    }
    // stage A1^T all s: a1t[s][v][u]
    for (int i = tid; i < 3 * 1024; i += 256) {
        int s = i >> 10;
        int v = (i >> 5) & 31;
        int u = i & 31;
        uint32_t val = 0u;
        if (v < VV && u < VV)
            val = f2tf32(g_A1[(s * NB + n) * 625 + u * 25 + v]);
        a1t[s * FZ_A1S + v * FZ_A1_STR + u] = val;
    }
    // zero hs rows u=25..31 (stage2 K pad; B-side also zero, belt+braces)
    for (int i = tid; i < 7 * 256; i += 256) {
        int u = 25 + i / 256;  // one row per pass (i/256 in 0..6)
        hs[u * FZ_HS_STR + (i & 255)] = 0u;
    }

    float acc2[2][4][4];
#pragma unroll
    for (int mi = 0; mi < 2; ++mi)
#pragma unroll
        for (int ni = 0; ni < 4; ++ni)
#pragma unroll
            for (int q = 0; q < 4; ++q) acc2[mi][ni][q] = 0.f;

#pragma unroll 1
    for (int s = 0; s < SS; ++s) {
        __syncthreads();   // prev stage2 reads done; wB free
        for (int i = tid; i < 4096; i += 256) {
            int c = i >> 6, o = i & 63;
            wB[c * FZ_WB_STR + o] = g_Wh[s * 4096 + i];
        }
        __syncthreads();

        // ---- stage1: h = x^T . W  (warp = 16 rows of p) ----
        float acc1[8][4];
#pragma unroll
        for (int ni = 0; ni < 8; ++ni)
#pragma unroll
            for (int q = 0; q < 4; ++q) acc1[ni][q] = 0.f;

#pragma unroll
        for (int kk = 0; kk < 8; ++kk) {
            const int kb = kk * 8;
            uint32_t af[4];
            {
                const uint32_t* pA = &xB[(kb + lr) * FZ_XB_STR + warp * 16 + lq];
                af[0] = pA[0];
                af[1] = pA[8];
                af[2] = pA[4 * FZ_XB_STR];
                af[3] = pA[4 * FZ_XB_STR + 8];
            }
#pragma unroll
            for (int ni = 0; ni < 8; ++ni) {
                uint32_t bf[2];
                const uint32_t* pB = &wB[(kb + lr) * FZ_WB_STR + ni * 8 + lq];
                bf[0] = pB[0];
                bf[1] = pB[4 * FZ_WB_STR];
                mma_tf32(acc1[ni], af, bf);
            }
        }

        // ---- transpose-store h into hs[u][tl*64+o] ----
#pragma unroll
        for (int ni = 0; ni < 8; ++ni)
#pragma unroll
            for (int q = 0; q < 4; ++q) {
                int p = warp * 16 + lq + (q >> 1) * 8;
                int o = ni * 8 + 2 * lr + (q & 1);
                if (p < 100) {
                    int tl = p / 25, u = p % 25;
                    hs[u * FZ_HS_STR + tl * 64 + o] = f2tf32(acc1[ni][q]);
                }
            }
        __syncthreads();

        // ---- stage2: z += hs^T . a1t_s ----
#pragma unroll
        for (int kk = 0; kk < 4; ++kk) {
            const int kb = kk * 8;
            uint32_t af[2][4];
#pragma unroll
            for (int mi = 0; mi < 2; ++mi) {
                const uint32_t* pA = &hs[(kb + lr) * FZ_HS_STR + warp * 32 + mi * 16 + lq];
                af[mi][0] = pA[0];
                af[mi][1] = pA[8];
                af[mi][2] = pA[4 * FZ_HS_STR];
                af[mi][3] = pA[4 * FZ_HS_STR + 8];
            }
            uint32_t bf[4][2];
#pragma unroll
            for (int ni = 0; ni < 4; ++ni) {
                const uint32_t* pB = &a1t[s * FZ_A1S + (ni * 8 + lq) * FZ_A1_STR + kb + lr];
                bf[ni][0] = pB[0];
                bf[ni][1] = pB[4];
            }
#pragma unroll
            for (int mi = 0; mi < 2; ++mi)
#pragma unroll
                for (int ni = 0; ni < 4; ++ni)
                    mma_tf32(acc2[mi][ni], af[mi], bf[ni]);
        }
    }

    // epilogue: BN + residual + relu
#pragma unroll
    for (int mi = 0; mi < 2; ++mi) {
#pragma unroll
        for (int ni = 0; ni < 4; ++ni) {
#pragma unroll
            for (int q = 0; q < 4; ++q) {
                int r = warp * 32 + mi * 16 + lq + (q >> 1) * 8;
                int v = ni * 8 + 2 * lr + (q & 1);
                if (v < VV) {
                    int tl = r >> 6, o = r & 63;
                    int gi = ((n * CH + o) * TT + t0 + tl) * VV + v;
                    float val = fmaf(acc2[mi][ni][q] + g_btot[o], g_bnscale[o], g_bnbias[o])
                                + x[gi];
                    out[gi] = fmaxf(val, 0.f);
                }
            }
        }
    }
}

// ---------------- launch ----------------
extern "C" void kernel_launch(void* const* d_in, const int* in_sizes, int n_in,
                              void* d_out, int out_size)
{
    const float* x   = (const float*)d_in[0];
    const float* w5  = (const float*)d_in[1];
    const float* A   = (const float*)d_in[2];
    const float* PA  = (const float*)d_in[3];
    const float* Wd  = (const float*)d_in[4];
    const float* bd  = (const float*)d_in[5];
    const float* WT1 = (const float*)d_in[6];
    const float* bT1 = (const float*)d_in[7];
    const float* WT2 = (const float*)d_in[8];
    const float* bT2 = (const float*)d_in[9];
    const float* bng = (const float*)d_in[10];
    const float* bnb = (const float*)d_in[11];
    const float* bnm = (const float*)d_in[12];
    const float* bnv = (const float*)d_in[13];
    float* out = (float*)d_out;

    cudaFuncSetAttribute(tc_conv,  cudaFuncAttributeMaxDynamicSharedMemorySize, CONV_SMEM);
    cudaFuncSetAttribute(fz_kernel, cudaFuncAttributeMaxDynamicSharedMemorySize, FZ_SMEM);

    prep1_kernel<<<2, 256>>>(A, PA);
    prep2_kernel<<<4, 256>>>(w5, WT1, WT2);
    prep3_kernel<<<4, 256>>>(w5, Wd, bd, bT1, bT2, bng, bnb, bnm, bnv);
    tc_conv<<<dim3(75, NB), 256, CONV_SMEM>>>(x);    // profiled slot (index 3)
    att_kernel<<<dim3(SS * NB, KSPLIT), 128>>>();
    soft_kernel<<<SS * NB, 32>>>();
    fz_kernel<<<dim3(75, NB), 256, FZ_SMEM>>>(x, out);
}